// round 3
// baseline (speedup 1.0000x reference)
#include <cuda_runtime.h>
#include <cstdint>

// ---------------- problem constants ----------------
#define N_ATOMS_MAX 131072
#define DQ      256
#define H1      512
#define NTYPE   4
#define TILE_M  128
#define MAX_TILES (N_ATOMS_MAX / TILE_M + NTYPE)  // 1028

// smem layout (float offsets)
#define SA_STRIDE 260          // 256 + 4 pad (stride%32 == 4 -> conflict-free frags)
#define SB_STRIDE 68           // 64 + 4 pad
#define SB_CHUNK  (128 * SB_STRIDE)   // one B stage: 128 H1-rows x 64 K floats (padded)

#define F_OFF_F    0                   // s_F[128]
#define F_OFF_IDX  128                 // s_idx[128] (ints)
#define F_OFF_B0   256                 // s_b0[512]
#define F_OFF_W1   768                 // s_w1[512]
#define F_OFF_A    1280                // s_A[128*260]
#define F_OFF_B    (1280 + 128*SA_STRIDE)   // s_B[2][SB_CHUNK]
#define SMEM_FLOATS (F_OFF_B + 2*SB_CHUNK)
#define SMEM_BYTES  (SMEM_FLOATS * 4)  // 207,872 B

// ---------------- device scratch (no runtime allocation allowed) ---------
__device__ float g_W0T[NTYPE * H1 * DQ];     // W0 transposed + tf32-rounded: [t][j][k]
__device__ int   g_idx[N_ATOMS_MAX];         // atom ids grouped by type
__device__ int   g_cnt[NTYPE];
__device__ int   g_base[NTYPE];
__device__ int   g_cursor[NTYPE];
__device__ int   g_tileT[MAX_TILES];
__device__ int   g_tileLT[MAX_TILES];
__device__ int   g_ntiles;

// ---------------- helpers ----------------
static __device__ __forceinline__ uint32_t smem_u32(const void* p) {
    uint32_t a;
    asm("{ .reg .u64 t; cvta.to.shared.u64 t, %1; cvt.u32.u64 %0, t; }" : "=r"(a) : "l"(p));
    return a;
}
static __device__ __forceinline__ void cp16(uint32_t dst, const void* src) {
    asm volatile("cp.async.cg.shared.global [%0], [%1], 16;" :: "r"(dst), "l"(src));
}
static __device__ __forceinline__ float tf32_rna(float v) {
    uint32_t o;
    asm("cvt.rna.tf32.f32 %0, %1;" : "=r"(o) : "f"(v));
    return __uint_as_float(o);
}
static __device__ __forceinline__ float tanh_fast(float x) {
    float y;
    asm("tanh.approx.f32 %0, %1;" : "=f"(y) : "f"(x));
    return y;
}
static __device__ __forceinline__ void mma_tf32(float* c, const uint32_t* a,
                                                uint32_t b0, uint32_t b1) {
    asm volatile(
        "mma.sync.aligned.m16n8k8.row.col.f32.tf32.tf32.f32 "
        "{%0,%1,%2,%3}, {%4,%5,%6,%7}, {%8,%9}, {%0,%1,%2,%3};"
        : "+f"(c[0]), "+f"(c[1]), "+f"(c[2]), "+f"(c[3])
        : "r"(a[0]), "r"(a[1]), "r"(a[2]), "r"(a[3]), "r"(b0), "r"(b1));
}

// ---------------- prep kernels ----------------
__global__ void k_zero() {
    if (threadIdx.x < NTYPE) g_cnt[threadIdx.x] = 0;
}

__global__ void k_hist(const int* __restrict__ Z, int n) {
    __shared__ int h[NTYPE];
    if (threadIdx.x < NTYPE) h[threadIdx.x] = 0;
    __syncthreads();
    for (int i = blockIdx.x * blockDim.x + threadIdx.x; i < n; i += gridDim.x * blockDim.x)
        atomicAdd(&h[Z[i]], 1);
    __syncthreads();
    if (threadIdx.x < NTYPE) atomicAdd(&g_cnt[threadIdx.x], h[threadIdx.x]);
}

__global__ void k_offsets() {
    if (threadIdx.x == 0 && blockIdx.x == 0) {
        int b = 0, ti = 0;
        for (int t = 0; t < NTYPE; t++) {
            g_base[t] = b;
            g_cursor[t] = b;
            int c = g_cnt[t];
            b += c;
            int nt = (c + TILE_M - 1) / TILE_M;
            for (int lt = 0; lt < nt; lt++) { g_tileT[ti] = t; g_tileLT[ti] = lt; ti++; }
        }
        g_ntiles = ti;
    }
}

__global__ void k_scatter(const int* __restrict__ Z, int n) {
    int i = blockIdx.x * blockDim.x + threadIdx.x;
    if (i >= n) return;  // n is a multiple of 256 -> warps stay fully converged
    int z = Z[i];
    int lane = threadIdx.x & 31;
#pragma unroll
    for (int t = 0; t < NTYPE; t++) {
        unsigned m = __ballot_sync(0xffffffffu, z == t);
        if (z == t) {
            int leader = __ffs(m) - 1;
            int rank = __popc(m & ((1u << lane) - 1u));
            int base = 0;
            if (lane == leader) base = atomicAdd(&g_cursor[t], __popc(m));
            base = __shfl_sync(m, base, leader);
            g_idx[base + rank] = i;
        }
    }
}

// W0 [T][DQ][H1] -> g_W0T [T][H1][DQ], rounded to tf32 (rna) so the MMA's
// RZ truncation costs nothing.
__global__ void k_transpose(const float* __restrict__ W0) {
    __shared__ float tile[32][33];
    int t = blockIdx.z;
    int k0 = blockIdx.x * 32;   // DQ dim
    int j0 = blockIdx.y * 32;   // H1 dim
    int x = threadIdx.x, y0 = threadIdx.y;  // 32 x 8
#pragma unroll
    for (int dy = 0; dy < 32; dy += 8) {
        int k = k0 + y0 + dy, j = j0 + x;
        tile[y0 + dy][x] = W0[((size_t)t * DQ + k) * H1 + j];
    }
    __syncthreads();
#pragma unroll
    for (int dy = 0; dy < 32; dy += 8) {
        int j = j0 + y0 + dy, k = k0 + x;
        g_W0T[((size_t)t * H1 + j) * DQ + k] = tf32_rna(tile[x][y0 + dy]);
    }
}

// ---------------- main fused GEMM + tanh + dot kernel ----------------
// chunk ci = nc*4 + kc : B rows [nc*128, +128), K cols [kc*64, +64)
static __device__ __forceinline__ void load_B_chunk(int ci, float* s_B_stage,
                                                    const float* __restrict__ w0t,
                                                    uint32_t sB_u32, int tid) {
    int nc = ci >> 2, kc = ci & 3;
#pragma unroll
    for (int o = 0; o < 8; o++) {
        int lin = o * 256 + tid;       // 2048 tasks: (row, 16B seg)
        int row = lin >> 4, seg = lin & 15;
        const float* src = w0t + (size_t)(nc * 128 + row) * DQ + kc * 64 + seg * 4;
        cp16(sB_u32 + (row * SB_STRIDE + seg * 4) * 4, src);
    }
    asm volatile("cp.async.commit_group;" ::: "memory");
}

__global__ void __launch_bounds__(256, 1)
k_gemm(const float* __restrict__ q, const float* __restrict__ b0,
       const float* __restrict__ W1, const float* __restrict__ b1v,
       float* __restrict__ out) {
    extern __shared__ float smem[];
    const int tid = threadIdx.x;
    const int wid = tid >> 5, lane = tid & 31;
    const int g = lane >> 2, tig = lane & 3;
    const int warpM = wid >> 1, warpN = wid & 1;
    const int bid = blockIdx.x;

    if (bid >= g_ntiles) return;

    const int t = g_tileT[bid], lt = g_tileLT[bid];
    const int cnt = g_cnt[t], base = g_base[t];
    const int row0 = lt * TILE_M;

    float* s_F  = smem + F_OFF_F;
    int*   s_idx = (int*)(smem + F_OFF_IDX);
    float* s_b0 = smem + F_OFF_B0;
    float* s_w1 = smem + F_OFF_W1;
    float* s_A  = smem + F_OFF_A;
    float* s_B  = smem + F_OFF_B;

    if (tid < TILE_M) {
        int r = row0 + tid;
        s_idx[tid] = g_idx[base + (r < cnt ? r : row0)];  // pad with a valid row
        s_F[tid] = 0.0f;
    }
    for (int i = tid; i < H1; i += 256) {
        s_b0[i] = b0[t * H1 + i];
        s_w1[i] = W1[t * H1 + i];
    }
    __syncthreads();   // s_idx visible for the A gather

    const float* w0t = g_W0T + (size_t)t * H1 * DQ;
    const uint32_t sB_u32_0 = smem_u32(s_B);

    // B prologue: chunks 0, 1 in flight
    load_B_chunk(0, s_B, w0t, sB_u32_0, tid);
    load_B_chunk(1, s_B + SB_CHUNK, w0t, sB_u32_0 + SB_CHUNK * 4, tid);

    // A gather: 128 rows x 256 floats = 8192 16B segments (32 / thread)
    // LDG.128 -> tf32 rna -> STS.128
#pragma unroll
    for (int o = 0; o < 32; o++) {
        int lin = o * 256 + tid;       // 8192 tasks: (row, 16B seg)
        int row = lin >> 6, seg = lin & 63;
        const float4 v = *(const float4*)(q + (size_t)s_idx[row] * DQ + seg * 4);
        float4 w;
        w.x = tf32_rna(v.x); w.y = tf32_rna(v.y);
        w.z = tf32_rna(v.z); w.w = tf32_rna(v.w);
        *(float4*)(s_A + row * SA_STRIDE + seg * 4) = w;
    }

    const float b1s = b1v[0];

#pragma unroll 1
    for (int nc = 0; nc < 4; nc++) {
        float acc[2][8][4];
#pragma unroll
        for (int i = 0; i < 2; i++)
#pragma unroll
            for (int j = 0; j < 8; j++)
#pragma unroll
                for (int c = 0; c < 4; c++) acc[i][j][c] = 0.0f;

#pragma unroll 1
        for (int kc = 0; kc < 4; kc++) {
            const int ci = nc * 4 + kc;
            const int buf = ci & 1;
            if (ci < 15) asm volatile("cp.async.wait_group 1;" ::: "memory");
            else         asm volatile("cp.async.wait_group 0;" ::: "memory");
            __syncthreads();   // B(ci) visible (and A STS on ci==0)

            const float* Bs = s_B + buf * SB_CHUNK;
#pragma unroll
            for (int ks = 0; ks < 8; ks++) {
                const int k0 = kc * 64 + ks * 8;
                uint32_t a[2][4];
#pragma unroll
                for (int i = 0; i < 2; i++) {
                    const int r = warpM * 32 + i * 16 + g;
                    a[i][0] = __float_as_uint(s_A[r * SA_STRIDE + k0 + tig]);
                    a[i][1] = __float_as_uint(s_A[(r + 8) * SA_STRIDE + k0 + tig]);
                    a[i][2] = __float_as_uint(s_A[r * SA_STRIDE + k0 + 4 + tig]);
                    a[i][3] = __float_as_uint(s_A[(r + 8) * SA_STRIDE + k0 + 4 + tig]);
                }
#pragma unroll
                for (int j = 0; j < 8; j++) {
                    const int n = warpN * 64 + j * 8 + g;
                    const uint32_t bb0 = __float_as_uint(Bs[n * SB_STRIDE + ks * 8 + tig]);
                    const uint32_t bb1 = __float_as_uint(Bs[n * SB_STRIDE + ks * 8 + 4 + tig]);
                    mma_tf32(acc[0][j], a[0], bb0, bb1);
                    mma_tf32(acc[1][j], a[1], bb0, bb1);
                }
            }
            __syncthreads();   // all warps done reading buf
            if (ci + 2 < 16)
                load_B_chunk(ci + 2, s_B + buf * SB_CHUNK, w0t,
                             sB_u32_0 + buf * SB_CHUNK * 4, tid);
        }

        // ---- per-N-chunk epilogue: tanh(h + b0) * W1, reduce over n ----
        float fa[4] = {0.0f, 0.0f, 0.0f, 0.0f};
#pragma unroll
        for (int i = 0; i < 2; i++)
#pragma unroll
            for (int j = 0; j < 8; j++)
#pragma unroll
                for (int c = 0; c < 4; c++) {
                    const int n_g = nc * 128 + warpN * 64 + j * 8 + tig * 2 + (c & 1);
                    const float h = tanh_fast(acc[i][j][c] + s_b0[n_g]);
                    fa[i * 2 + (c >> 1)] = fmaf(h, s_w1[n_g], fa[i * 2 + (c >> 1)]);
                }
#pragma unroll
        for (int s = 0; s < 4; s++) {
            fa[s] += __shfl_xor_sync(0xffffffffu, fa[s], 1);
            fa[s] += __shfl_xor_sync(0xffffffffu, fa[s], 2);
        }
        if (tig == 0) {
#pragma unroll
            for (int s = 0; s < 4; s++) {
                const int m = warpM * 32 + (s >> 1) * 16 + (s & 1) * 8 + g;
                atomicAdd(&s_F[m], fa[s]);
            }
        }
    }

    __syncthreads();
    if (tid < TILE_M) {
        if (row0 + tid < cnt) out[s_idx[tid]] = s_F[tid] + b1s;
    }
}

// ---------------- launch ----------------
extern "C" void kernel_launch(void* const* d_in, const int* in_sizes, int n_in,
                              void* d_out, int out_size) {
    const float* q  = (const float*)d_in[0];
    const int*   Z  = (const int*)d_in[1];
    const float* W0 = (const float*)d_in[2];
    const float* b0 = (const float*)d_in[3];
    const float* W1 = (const float*)d_in[4];
    const float* b1 = (const float*)d_in[5];
    float* out = (float*)d_out;
    int n = in_sizes[1];  // N atoms

    k_zero<<<1, 32>>>();
    k_hist<<<512, 256>>>(Z, n);
    k_offsets<<<1, 32>>>();
    k_scatter<<<(n + 255) / 256, 256>>>(Z, n);
    k_transpose<<<dim3(DQ / 32, H1 / 32, NTYPE), dim3(32, 8)>>>(W0);

    cudaFuncSetAttribute(k_gemm, cudaFuncAttributeMaxDynamicSharedMemorySize, SMEM_BYTES);
    k_gemm<<<MAX_TILES, 256, SMEM_BYTES>>>(q, b0, W1, b1, out);
}

// round 4
// speedup vs baseline: 1.0022x; 1.0022x over previous
#include <cuda_runtime.h>
#include <cstdint>

// ---------------- problem constants ----------------
#define N_ATOMS_MAX 131072
#define DQ      256
#define H1      512
#define NTYPE   4
#define TILE_M  128
#define MAX_TILES (N_ATOMS_MAX / TILE_M + NTYPE)  // 1028
#define HIST_BLOCKS 256
#define BLOCK   512

// ---------------- smem layout (float offsets) ----------------
#define SA_STRIDE 260                 // 256 + 4 pad (row step = 4 banks -> conflict-free A frags)
#define SB_STRIDE 80                  // 64 data + 16 pad (row step = 4 x 16B-lanes mod 8 -> .128 clean)
#define SB_STAGE  (64 * SB_STRIDE)    // 5120 floats = 20 KB
#define F_OFF_F    0                  // s_F[128]
#define F_OFF_IDX  128                // s_idx[128]
#define F_OFF_B0   256                // s_b0[512]
#define F_OFF_W1   768                // s_w1[512]
#define F_OFF_A    1280               // s_A[128*260]
#define F_OFF_B    (F_OFF_A + 128 * SA_STRIDE)    // 34560
#define SMEM_FLOATS (F_OFF_B + 4 * SB_STAGE)      // 55040
#define SMEM_BYTES  (SMEM_FLOATS * 4)             // 220160 B

// ---------------- device scratch ----------------
__device__ float g_W0T[NTYPE * H1 * DQ];   // W0^T, tf32-rounded, K-permuted: [t][j][kperm]
__device__ int   g_idx[N_ATOMS_MAX];
__device__ int   g_part[HIST_BLOCKS][NTYPE];
__device__ int   g_cnt[NTYPE];
__device__ int   g_base[NTYPE];
__device__ int   g_cursor[NTYPE];
__device__ int   g_tileT[MAX_TILES];
__device__ int   g_tileLT[MAX_TILES];
__device__ int   g_ntiles;

// ---------------- helpers ----------------
static __device__ __forceinline__ uint32_t smem_u32(const void* p) {
    uint32_t a;
    asm("{ .reg .u64 t; cvta.to.shared.u64 t, %1; cvt.u32.u64 %0, t; }" : "=r"(a) : "l"(p));
    return a;
}
static __device__ __forceinline__ void cp16(uint32_t dst, const void* src) {
    asm volatile("cp.async.cg.shared.global [%0], [%1], 16;" :: "r"(dst), "l"(src));
}
static __device__ __forceinline__ float tf32_rna(float v) {
    uint32_t o;
    asm("cvt.rna.tf32.f32 %0, %1;" : "=r"(o) : "f"(v));
    return __uint_as_float(o);
}
static __device__ __forceinline__ float tanh_fast(float x) {
    float y;
    asm("tanh.approx.f32 %0, %1;" : "=f"(y) : "f"(x));
    return y;
}
static __device__ __forceinline__ void mma_tf32(float* c, uint32_t a0, uint32_t a1,
                                                uint32_t a2, uint32_t a3,
                                                uint32_t b0, uint32_t b1) {
    asm volatile(
        "mma.sync.aligned.m16n8k8.row.col.f32.tf32.tf32.f32 "
        "{%0,%1,%2,%3}, {%4,%5,%6,%7}, {%8,%9}, {%0,%1,%2,%3};"
        : "+f"(c[0]), "+f"(c[1]), "+f"(c[2]), "+f"(c[3])
        : "r"(a0), "r"(a1), "r"(a2), "r"(a3), "r"(b0), "r"(b1));
}
// K permutation within each 16-col group: pos = (c&3)*4 + ((c>>2)&3)
static __device__ __forceinline__ int kperm(int k) {
    return (k & ~15) | ((k & 3) << 2) | ((k >> 2) & 3);
}

// ---------------- prep kernels ----------------
__global__ void k_hist(const int* __restrict__ Z, int n) {
    __shared__ int h[NTYPE];
    if (threadIdx.x < NTYPE) h[threadIdx.x] = 0;
    __syncthreads();
    for (int i = blockIdx.x * blockDim.x + threadIdx.x; i < n; i += gridDim.x * blockDim.x)
        atomicAdd(&h[Z[i]], 1);
    __syncthreads();
    if (threadIdx.x < NTYPE) g_part[blockIdx.x][threadIdx.x] = h[threadIdx.x];
}

__global__ void k_offsets() {
    __shared__ int cnt[NTYPE];
    __shared__ int ts[NTYPE + 1];
    if (threadIdx.x < NTYPE) {
        int s = 0;
        for (int i = 0; i < HIST_BLOCKS; i++) s += g_part[i][threadIdx.x];
        cnt[threadIdx.x] = s;
        g_cnt[threadIdx.x] = s;
    }
    __syncthreads();
    if (threadIdx.x == 0) {
        int b = 0, ti = 0;
        for (int t = 0; t < NTYPE; t++) {
            g_base[t] = b; g_cursor[t] = b; b += cnt[t];
            ts[t] = ti; ti += (cnt[t] + TILE_M - 1) / TILE_M;
        }
        ts[NTYPE] = ti;
        g_ntiles = ti;
    }
    __syncthreads();
    const int nt = ts[NTYPE];
    for (int ti = threadIdx.x; ti < nt; ti += blockDim.x) {
        int t = 0;
        while (t < NTYPE - 1 && ti >= ts[t + 1]) t++;
        g_tileT[ti] = t;
        g_tileLT[ti] = ti - ts[t];
    }
}

__global__ void k_scatter(const int* __restrict__ Z, int n) {
    int i = blockIdx.x * blockDim.x + threadIdx.x;
    if (i >= n) return;  // n multiple of 256 -> warps stay converged
    int z = Z[i];
    int lane = threadIdx.x & 31;
#pragma unroll
    for (int t = 0; t < NTYPE; t++) {
        unsigned m = __ballot_sync(0xffffffffu, z == t);
        if (z == t) {
            int leader = __ffs(m) - 1;
            int rank = __popc(m & ((1u << lane) - 1u));
            int base = 0;
            if (lane == leader) base = atomicAdd(&g_cursor[t], __popc(m));
            base = __shfl_sync(m, base, leader);
            g_idx[base + rank] = i;
        }
    }
}

// W0 [T][DQ][H1] -> g_W0T [T][H1][kperm(DQ)], tf32-rna rounded.
__global__ void k_transpose(const float* __restrict__ W0) {
    __shared__ float tile[32][33];
    int t = blockIdx.z;
    int k0 = blockIdx.x * 32;   // DQ dim
    int j0 = blockIdx.y * 32;   // H1 dim
    int x = threadIdx.x, y0 = threadIdx.y;  // 32 x 8
#pragma unroll
    for (int dy = 0; dy < 32; dy += 8) {
        int k = k0 + y0 + dy, j = j0 + x;
        tile[y0 + dy][x] = W0[((size_t)t * DQ + k) * H1 + j];
    }
    __syncthreads();
#pragma unroll
    for (int dy = 0; dy < 32; dy += 8) {
        int j = j0 + y0 + dy, k = k0 + x;
        g_W0T[((size_t)t * H1 + j) * DQ + kperm(k)] = tf32_rna(tile[x][y0 + dy]);
    }
}

// ---------------- main fused GEMM + tanh + dot kernel ----------------
// chunk ci = 0..31: nc = ci>>3 (128 n-cols), half = (ci>>2)&1 (64 n-cols), kc = ci&3 (64 K)
// stage slot = ci & 3
static __device__ __forceinline__ void load_B_stage(int ci, uint32_t sB_u32,
                                                    const float* __restrict__ w0t, int tid) {
    const int nc = ci >> 3, half = (ci >> 2) & 1, kc = ci & 3;
    const int slot = ci & 3;
    const uint32_t dst0 = sB_u32 + slot * (SB_STAGE * 4);
#pragma unroll
    for (int o = 0; o < 2; o++) {
        int lin = o * BLOCK + tid;          // 1024 tasks: 64 rows x 16 segs
        int row = lin >> 4, seg = lin & 15;
        const float* src = w0t + (size_t)(nc * 128 + half * 64 + row) * DQ + kc * 64 + seg * 4;
        cp16(dst0 + (row * SB_STRIDE + seg * 4) * 4, src);
    }
    asm volatile("cp.async.commit_group;" ::: "memory");
}

__global__ void __launch_bounds__(BLOCK, 1)
k_gemm(const float* __restrict__ q, const float* __restrict__ b0,
       const float* __restrict__ W1, const float* __restrict__ b1v,
       float* __restrict__ out) {
    extern __shared__ float smem[];
    const int tid = threadIdx.x;
    const int wid = tid >> 5, lane = tid & 31;
    const int g = lane >> 2, tig = lane & 3;
    const int warpM = wid >> 2, warpN = wid & 3;   // 4M x 4N warps
    const int bid = blockIdx.x;

    if (bid >= g_ntiles) return;

    const int t = g_tileT[bid], lt = g_tileLT[bid];
    const int cnt = g_cnt[t], base = g_base[t];
    const int row0 = lt * TILE_M;

    float* s_F   = smem + F_OFF_F;
    int*   s_idx = (int*)(smem + F_OFF_IDX);
    float* s_b0  = smem + F_OFF_B0;
    float* s_w1  = smem + F_OFF_W1;
    float* s_A   = smem + F_OFF_A;
    float* s_B   = smem + F_OFF_B;

    if (tid < TILE_M) {
        int r = row0 + tid;
        s_idx[tid] = g_idx[base + (r < cnt ? r : row0)];
        s_F[tid] = 0.0f;
    }
    if (tid < H1) {
        s_b0[tid] = b0[t * H1 + tid];
        s_w1[tid] = W1[t * H1 + tid];
    }
    __syncthreads();   // s_idx visible

    const float* w0t = g_W0T + (size_t)t * H1 * DQ;
    const uint32_t sB_u32 = smem_u32(s_B);

    // pipeline prologue: stages 0, 1, 2 in flight
    load_B_stage(0, sB_u32, w0t, tid);
    load_B_stage(1, sB_u32, w0t, tid);
    load_B_stage(2, sB_u32, w0t, tid);

    // A gather: 128 rows x 256 floats = 8192 16B segs (16/thread), tf32-rna on the fly
#pragma unroll
    for (int o = 0; o < 16; o++) {
        int lin = o * BLOCK + tid;
        int row = lin >> 6, seg = lin & 63;
        const float4 v = *(const float4*)(q + (size_t)s_idx[row] * DQ + seg * 4);
        float4 w;
        w.x = tf32_rna(v.x); w.y = tf32_rna(v.y);
        w.z = tf32_rna(v.z); w.w = tf32_rna(v.w);
        *(float4*)(s_A + row * SA_STRIDE + seg * 4) = w;
    }

    const float b1s = b1v[0];

#pragma unroll 1
    for (int g8 = 0; g8 < 8; g8++) {             // (nc, half) groups
        const int nc = g8 >> 1, half = g8 & 1;
        float acc[2][2][4];
#pragma unroll
        for (int i = 0; i < 2; i++)
#pragma unroll
            for (int j = 0; j < 2; j++)
#pragma unroll
                for (int c = 0; c < 4; c++) acc[i][j][c] = 0.0f;

#pragma unroll 1
        for (int kc = 0; kc < 4; kc++) {
            const int ci = g8 * 4 + kc;
            if (ci < 30)       asm volatile("cp.async.wait_group 2;" ::: "memory");
            else if (ci == 30) asm volatile("cp.async.wait_group 1;" ::: "memory");
            else               asm volatile("cp.async.wait_group 0;" ::: "memory");
            __syncthreads();   // stage ci visible to all; all warps done with chunk ci-1

            if (ci + 3 < 32) load_B_stage(ci + 3, sB_u32, w0t, tid);  // into slot (ci-1)&3

            const float* Bs = s_B + (ci & 3) * SB_STAGE;
#pragma unroll
            for (int p = 0; p < 4; p++) {        // k16 pairs
                const int k0 = kc * 64 + p * 16;
                uint32_t a[2][8];
#pragma unroll
                for (int i = 0; i < 2; i++) {
                    const float* Ar = s_A + (warpM * 32 + i * 16 + g) * SA_STRIDE + k0;
                    a[i][0] = __float_as_uint(Ar[tig]);
                    a[i][1] = __float_as_uint(Ar[8 * SA_STRIDE + tig]);
                    a[i][2] = __float_as_uint(Ar[4 + tig]);
                    a[i][3] = __float_as_uint(Ar[8 * SA_STRIDE + 4 + tig]);
                    a[i][4] = __float_as_uint(Ar[8 + tig]);
                    a[i][5] = __float_as_uint(Ar[8 * SA_STRIDE + 8 + tig]);
                    a[i][6] = __float_as_uint(Ar[12 + tig]);
                    a[i][7] = __float_as_uint(Ar[8 * SA_STRIDE + 12 + tig]);
                }
#pragma unroll
                for (int j = 0; j < 2; j++) {
                    const int n = warpN * 16 + j * 8 + g;
                    // permuted layout: one LDS.128 = cols {tig, tig+4, tig+8, tig+12}
                    const float4 bv = *(const float4*)(Bs + n * SB_STRIDE + p * 16 + tig * 4);
                    const uint32_t bb0 = __float_as_uint(bv.x), bb1 = __float_as_uint(bv.y);
                    const uint32_t bb2 = __float_as_uint(bv.z), bb3 = __float_as_uint(bv.w);
                    mma_tf32(acc[0][j], a[0][0], a[0][1], a[0][2], a[0][3], bb0, bb1);
                    mma_tf32(acc[1][j], a[1][0], a[1][1], a[1][2], a[1][3], bb0, bb1);
                    mma_tf32(acc[0][j], a[0][4], a[0][5], a[0][6], a[0][7], bb2, bb3);
                    mma_tf32(acc[1][j], a[1][4], a[1][5], a[1][6], a[1][7], bb2, bb3);
                }
            }
        }

        // ---- epilogue for this 64-col group: tanh(h + b0) * W1, reduce over n ----
        float fa[4] = {0.0f, 0.0f, 0.0f, 0.0f};
#pragma unroll
        for (int i = 0; i < 2; i++)
#pragma unroll
            for (int j = 0; j < 2; j++)
#pragma unroll
                for (int c = 0; c < 4; c++) {
                    const int colg = nc * 128 + half * 64 + warpN * 16 + j * 8 + tig * 2 + (c & 1);
                    const float h = tanh_fast(acc[i][j][c] + s_b0[colg]);
                    fa[i * 2 + (c >> 1)] = fmaf(h, s_w1[colg], fa[i * 2 + (c >> 1)]);
                }
#pragma unroll
        for (int s = 0; s < 4; s++) {
            fa[s] += __shfl_xor_sync(0xffffffffu, fa[s], 1);
            fa[s] += __shfl_xor_sync(0xffffffffu, fa[s], 2);
        }
        if (tig == 0) {
#pragma unroll
            for (int s = 0; s < 4; s++) {
                const int m = warpM * 32 + (s >> 1) * 16 + (s & 1) * 8 + g;
                atomicAdd(&s_F[m], fa[s]);
            }
        }
    }

    __syncthreads();
    if (tid < TILE_M) {
        if (row0 + tid < cnt) out[s_idx[tid]] = s_F[tid] + b1s;
    }
}

// ---------------- launch ----------------
extern "C" void kernel_launch(void* const* d_in, const int* in_sizes, int n_in,
                              void* d_out, int out_size) {
    const float* q  = (const float*)d_in[0];
    const int*   Z  = (const int*)d_in[1];
    const float* W0 = (const float*)d_in[2];
    const float* b0 = (const float*)d_in[3];
    const float* W1 = (const float*)d_in[4];
    const float* b1 = (const float*)d_in[5];
    float* out = (float*)d_out;
    int n = in_sizes[1];

    k_hist<<<HIST_BLOCKS, 256>>>(Z, n);
    k_offsets<<<1, 256>>>();
    k_scatter<<<(n + 255) / 256, 256>>>(Z, n);
    k_transpose<<<dim3(DQ / 32, H1 / 32, NTYPE), dim3(32, 8)>>>(W0);

    cudaFuncSetAttribute(k_gemm, cudaFuncAttributeMaxDynamicSharedMemorySize, SMEM_BYTES);
    k_gemm<<<MAX_TILES, BLOCK, SMEM_BYTES>>>(q, b0, W1, b1, out);
}

// round 6
// speedup vs baseline: 1.6414x; 1.6378x over previous
#include <cuda_runtime.h>
#include <cuda_fp16.h>
#include <cstdint>

// ---------------- problem constants ----------------
#define N_ATOMS_MAX 131072
#define DQ      256
#define H1      512
#define NTYPE   4
#define TILE_M  128
#define MAX_TILES (N_ATOMS_MAX / TILE_M + NTYPE)  // 1028
#define HIST_BLOCKS 256
#define BLOCK   512

// ---------------- smem layout (byte offsets) ----------------
#define SA_STRIDE_H 272               // halfs per A row: 256 + 16 pad (word stride 136 = 8 mod 32)
#define SB_STRIDE_H 144               // halfs per B row: 128 + 16 pad (word stride 72  = 8 mod 32)
#define SB_STAGE_B  (64 * SB_STRIDE_H * 2)   // 18432 B per stage
#define B_OFF_F    0                  // s_F[128] floats
#define B_OFF_IDX  512                // s_idx[128] ints
#define B_OFF_B0   1024               // s_b0[512] floats
#define B_OFF_W1   3072               // s_w1[512] floats
#define B_OFF_A    5120               // s_A: 128 * 544 B = 69632
#define B_OFF_B    (B_OFF_A + 128 * SA_STRIDE_H * 2)   // 74752
#define SMEM_BYTES (B_OFF_B + 4 * SB_STAGE_B)          // 148480 B

// ---------------- device scratch ----------------
__device__ __half g_W0H[NTYPE * H1 * DQ];  // W0^T fp16, K-interleaved: [t][j][kperm]
__device__ int    g_idx[N_ATOMS_MAX];
__device__ int    g_part[HIST_BLOCKS][NTYPE];
__device__ int    g_cnt[NTYPE];
__device__ int    g_base[NTYPE];
__device__ int    g_cursor[NTYPE];
__device__ int    g_tileT[MAX_TILES];
__device__ int    g_tileLT[MAX_TILES];
__device__ int    g_ntiles;

// ---------------- helpers ----------------
static __device__ __forceinline__ uint32_t smem_u32(const void* p) {
    uint32_t a;
    asm("{ .reg .u64 t; cvta.to.shared.u64 t, %1; cvt.u32.u64 %0, t; }" : "=r"(a) : "l"(p));
    return a;
}
static __device__ __forceinline__ void cp16(uint32_t dst, const void* src) {
    asm volatile("cp.async.cg.shared.global [%0], [%1], 16;" :: "r"(dst), "l"(src));
}
static __device__ __forceinline__ float tanh_fast(float x) {
    float y;
    asm("tanh.approx.f32 %0, %1;" : "=f"(y) : "f"(x));
    return y;
}
// pack two fp32 -> one u32 of fp16x2: lo gets 'lo', hi gets 'hi'
static __device__ __forceinline__ uint32_t pack_h2(float lo, float hi) {
    uint32_t r;
    asm("cvt.rn.f16x2.f32 %0, %1, %2;" : "=r"(r) : "f"(hi), "f"(lo));
    return r;
}
static __device__ __forceinline__ void mma_f16(float* c, uint32_t a0, uint32_t a1,
                                               uint32_t a2, uint32_t a3,
                                               uint32_t b0, uint32_t b1) {
    asm volatile(
        "mma.sync.aligned.m16n8k16.row.col.f32.f16.f16.f32 "
        "{%0,%1,%2,%3}, {%4,%5,%6,%7}, {%8,%9}, {%0,%1,%2,%3};"
        : "+f"(c[0]), "+f"(c[1]), "+f"(c[2]), "+f"(c[3])
        : "r"(a0), "r"(a1), "r"(a2), "r"(a3), "r"(b0), "r"(b1));
}
// K interleave within each 16-group: order [0,1,8,9, 2,3,10,11, 4,5,12,13, 6,7,14,15]
// inner i -> pos = ((i&7)>>1)*4 + ((i>>3)&1)*2 + (i&1)
static __device__ __forceinline__ int kperm16(int k) {
    return (k & ~15) | ((((k & 7) >> 1) << 2) | (((k >> 3) & 1) << 1) | (k & 1));
}

// ---------------- prep kernels ----------------
__global__ void k_hist(const int* __restrict__ Z, int n) {
    __shared__ int h[NTYPE];
    if (threadIdx.x < NTYPE) h[threadIdx.x] = 0;
    __syncthreads();
    for (int i = blockIdx.x * blockDim.x + threadIdx.x; i < n; i += gridDim.x * blockDim.x)
        atomicAdd(&h[Z[i]], 1);
    __syncthreads();
    if (threadIdx.x < NTYPE) g_part[blockIdx.x][threadIdx.x] = h[threadIdx.x];
}

__global__ void k_offsets() {
    __shared__ int cnt[NTYPE];
    __shared__ int ts[NTYPE + 1];
    if (threadIdx.x < NTYPE) {
        int s = 0;
        for (int i = 0; i < HIST_BLOCKS; i++) s += g_part[i][threadIdx.x];
        cnt[threadIdx.x] = s;
        g_cnt[threadIdx.x] = s;
    }
    __syncthreads();
    if (threadIdx.x == 0) {
        int b = 0, ti = 0;
        for (int t = 0; t < NTYPE; t++) {
            g_base[t] = b; g_cursor[t] = b; b += cnt[t];
            ts[t] = ti; ti += (cnt[t] + TILE_M - 1) / TILE_M;
        }
        ts[NTYPE] = ti;
        g_ntiles = ti;
    }
    __syncthreads();
    const int nt = ts[NTYPE];
    for (int ti = threadIdx.x; ti < nt; ti += blockDim.x) {
        int t = 0;
        while (t < NTYPE - 1 && ti >= ts[t + 1]) t++;
        g_tileT[ti] = t;
        g_tileLT[ti] = ti - ts[t];
    }
}

__global__ void k_scatter(const int* __restrict__ Z, int n) {
    int i = blockIdx.x * blockDim.x + threadIdx.x;
    if (i >= n) return;  // n multiple of 256 -> warps stay converged
    int z = Z[i];
    int lane = threadIdx.x & 31;
#pragma unroll
    for (int t = 0; t < NTYPE; t++) {
        unsigned m = __ballot_sync(0xffffffffu, z == t);
        if (z == t) {
            int leader = __ffs(m) - 1;
            int rank = __popc(m & ((1u << lane) - 1u));
            int base = 0;
            if (lane == leader) base = atomicAdd(&g_cursor[t], __popc(m));
            base = __shfl_sync(m, base, leader);
            g_idx[base + rank] = i;
        }
    }
}

// W0 [T][DQ][H1] fp32 -> g_W0H [T][H1][kperm16(DQ)] fp16 (rn)
__global__ void k_transpose(const float* __restrict__ W0) {
    __shared__ float tile[32][33];
    int t = blockIdx.z;
    int k0 = blockIdx.x * 32;   // DQ dim
    int j0 = blockIdx.y * 32;   // H1 dim
    int x = threadIdx.x, y0 = threadIdx.y;  // 32 x 8
#pragma unroll
    for (int dy = 0; dy < 32; dy += 8) {
        int k = k0 + y0 + dy, j = j0 + x;
        tile[y0 + dy][x] = W0[((size_t)t * DQ + k) * H1 + j];
    }
    __syncthreads();
#pragma unroll
    for (int dy = 0; dy < 32; dy += 8) {
        int j = j0 + y0 + dy, k = k0 + x;
        g_W0H[((size_t)t * H1 + j) * DQ + kperm16(k)] = __float2half_rn(tile[x][y0 + dy]);
    }
}

// ---------------- main fused GEMM + tanh + dot kernel ----------------
// 16 chunks: ci = ng*2 + kc  (ng = 64-row n-group 0..7, kc = K half 0..1), slot = ci & 3
static __device__ __forceinline__ void load_B_stage(int ci, uint32_t sB_u32,
                                                    const __half* __restrict__ w0h, int tid) {
    const int ng = ci >> 1, kc = ci & 1;
    const uint32_t dst0 = sB_u32 + (ci & 3) * SB_STAGE_B;
#pragma unroll
    for (int o = 0; o < 2; o++) {
        int lin = o * BLOCK + tid;          // 1024 tasks: 64 rows x 16 segs of 16 B
        int row = lin >> 4, seg = lin & 15;
        const __half* src = w0h + (size_t)(ng * 64 + row) * DQ + kc * 128 + seg * 8;
        cp16(dst0 + (row * SB_STRIDE_H + seg * 8) * 2, src);
    }
    asm volatile("cp.async.commit_group;" ::: "memory");
}

__global__ void __launch_bounds__(BLOCK, 1)
k_gemm(const float* __restrict__ q, const float* __restrict__ b0,
       const float* __restrict__ W1, const float* __restrict__ b1v,
       float* __restrict__ out) {
    extern __shared__ char smem[];
    const int tid = threadIdx.x;
    const int wid = tid >> 5, lane = tid & 31;
    const int g = lane >> 2, tig = lane & 3;
    const int warpM = wid >> 2, warpN = wid & 3;   // 4M x 4N warps
    const int bid = blockIdx.x;

    if (bid >= g_ntiles) return;

    const int t = g_tileT[bid], lt = g_tileLT[bid];
    const int cnt = g_cnt[t], base = g_base[t];
    const int row0 = lt * TILE_M;

    float*  s_F   = (float*)(smem + B_OFF_F);
    int*    s_idx = (int*)(smem + B_OFF_IDX);
    float*  s_b0  = (float*)(smem + B_OFF_B0);
    float*  s_w1  = (float*)(smem + B_OFF_W1);
    __half* s_A   = (__half*)(smem + B_OFF_A);
    __half* s_B   = (__half*)(smem + B_OFF_B);

    if (tid < TILE_M) {
        int r = row0 + tid;
        s_idx[tid] = g_idx[base + (r < cnt ? r : row0)];
        s_F[tid] = 0.0f;
    }
    if (tid < H1) {
        s_b0[tid] = b0[t * H1 + tid];
        s_w1[tid] = W1[t * H1 + tid];
    }
    __syncthreads();   // s_idx visible

    const __half* w0h = g_W0H + (size_t)t * H1 * DQ;
    const uint32_t sB_u32 = smem_u32(s_B);

    // pipeline prologue: stages 0, 1, 2 in flight
    load_B_stage(0, sB_u32, w0h, tid);
    load_B_stage(1, sB_u32, w0h, tid);
    load_B_stage(2, sB_u32, w0h, tid);

    // A gather: 128 rows x 16 k-groups; per task: 16 floats -> 16 halfs (perm) -> 32 B
#pragma unroll
    for (int o = 0; o < 4; o++) {
        int lin = o * BLOCK + tid;          // 2048 tasks
        int row = lin >> 4, grp = lin & 15;
        const float* src = q + (size_t)s_idx[row] * DQ + grp * 16;
        float v[16];
#pragma unroll
        for (int s = 0; s < 4; s++) {
            const float4 f4 = *(const float4*)(src + s * 4);
            v[s * 4 + 0] = f4.x; v[s * 4 + 1] = f4.y;
            v[s * 4 + 2] = f4.z; v[s * 4 + 3] = f4.w;
        }
        uint32_t w[8];
#pragma unroll
        for (int ww = 0; ww < 8; ww++) {
            // word ww holds inner k pair (i_lo, i_lo+1); perm order [0,1,8,9,2,3,10,11,...]
            const int i_lo = (ww & 1) * 8 + (ww >> 1) * 2;
            w[ww] = pack_h2(v[i_lo], v[i_lo + 1]);
        }
        uint32_t* dst = (uint32_t*)(s_A + row * SA_STRIDE_H + grp * 16);
        *(uint4*)(dst)     = make_uint4(w[0], w[1], w[2], w[3]);
        *(uint4*)(dst + 4) = make_uint4(w[4], w[5], w[6], w[7]);
    }

    const float b1s = b1v[0];

#pragma unroll 1
    for (int ng = 0; ng < 8; ng++) {            // 64-col n-groups
        float acc[2][2][4];
#pragma unroll
        for (int i = 0; i < 2; i++)
#pragma unroll
            for (int j = 0; j < 2; j++)
#pragma unroll
                for (int c = 0; c < 4; c++) acc[i][j][c] = 0.0f;

#pragma unroll 1
        for (int kc = 0; kc < 2; kc++) {
            const int ci = ng * 2 + kc;
            if (ci < 14)       asm volatile("cp.async.wait_group 2;" ::: "memory");
            else if (ci == 14) asm volatile("cp.async.wait_group 1;" ::: "memory");
            else               asm volatile("cp.async.wait_group 0;" ::: "memory");
            __syncthreads();   // stage ci visible; all warps done with stage ci-1

            if (ci + 3 < 16) load_B_stage(ci + 3, sB_u32, w0h, tid);

            const __half* Bs = s_B + (ci & 3) * (SB_STAGE_B / 2);
#pragma unroll
            for (int p = 0; p < 8; p++) {        // k16 steps within this K-half
                const int kofs = kc * 128 + p * 16;   // A k offset (halfs)
                uint2 a[2][2];
#pragma unroll
                for (int i = 0; i < 2; i++) {
                    const __half* Ar = s_A + (warpM * 32 + i * 16 + g) * SA_STRIDE_H + kofs + tig * 4;
                    a[i][0] = *(const uint2*)(Ar);                     // {a0, a2} for row r
                    a[i][1] = *(const uint2*)(Ar + 8 * SA_STRIDE_H);   // {a1, a3} for row r+8
                }
#pragma unroll
                for (int j = 0; j < 2; j++) {
                    const int n = warpN * 16 + j * 8 + g;
                    const uint2 bv = *(const uint2*)(Bs + n * SB_STRIDE_H + p * 16 + tig * 4);
                    mma_f16(acc[0][j], a[0][0].x, a[0][1].x, a[0][0].y, a[0][1].y, bv.x, bv.y);
                    mma_f16(acc[1][j], a[1][0].x, a[1][1].x, a[1][0].y, a[1][1].y, bv.x, bv.y);
                }
            }
        }

        // ---- epilogue for this 64-col group: tanh(h + b0) * W1, reduce over n ----
        float fa[4] = {0.0f, 0.0f, 0.0f, 0.0f};
#pragma unroll
        for (int i = 0; i < 2; i++)
#pragma unroll
            for (int j = 0; j < 2; j++)
#pragma unroll
                for (int c = 0; c < 4; c++) {
                    const int colg = ng * 64 + warpN * 16 + j * 8 + tig * 2 + (c & 1);
                    const float h = tanh_fast(acc[i][j][c] + s_b0[colg]);
                    fa[i * 2 + (c >> 1)] = fmaf(h, s_w1[colg], fa[i * 2 + (c >> 1)]);
                }
#pragma unroll
        for (int s = 0; s < 4; s++) {
            fa[s] += __shfl_xor_sync(0xffffffffu, fa[s], 1);
            fa[s] += __shfl_xor_sync(0xffffffffu, fa[s], 2);
        }
        if (tig == 0) {
#pragma unroll
            for (int s = 0; s < 4; s++) {
                const int m = warpM * 32 + (s >> 1) * 16 + (s & 1) * 8 + g;
                atomicAdd(&s_F[m], fa[s]);
            }
        }
    }

    __syncthreads();
    if (tid < TILE_M) {
        if (row0 + tid < cnt) out[s_idx[tid]] = s_F[tid] + b1s;
    }
}

// ---------------- launch ----------------
extern "C" void kernel_launch(void* const* d_in, const int* in_sizes, int n_in,
                              void* d_out, int out_size) {
    const float* q  = (const float*)d_in[0];
    const int*   Z  = (const int*)d_in[1];
    const float* W0 = (const float*)d_in[2];
    const float* b0 = (const float*)d_in[3];
    const float* W1 = (const float*)d_in[4];
    const float* b1 = (const float*)d_in[5];
    float* out = (float*)d_out;
    int n = in_sizes[1];

    k_hist<<<HIST_BLOCKS, 256>>>(Z, n);
    k_offsets<<<1, 256>>>();
    k_scatter<<<(n + 255) / 256, 256>>>(Z, n);
    k_transpose<<<dim3(DQ / 32, H1 / 32, NTYPE), dim3(32, 8)>>>(W0);

    cudaFuncSetAttribute(k_gemm, cudaFuncAttributeMaxDynamicSharedMemorySize, SMEM_BYTES);
    k_gemm<<<MAX_TILES, BLOCK, SMEM_BYTES>>>(q, b0, W1, b1, out);
}

// round 7
// speedup vs baseline: 1.7390x; 1.0594x over previous
#include <cuda_runtime.h>
#include <cuda_fp16.h>
#include <cstdint>

// ---------------- problem constants ----------------
#define N_ATOMS_MAX 131072
#define DQ      256
#define H1      512
#define NTYPE   4
#define TILE_M  256
#define MAX_TILES (N_ATOMS_MAX / TILE_M + NTYPE)  // 516
#define HIST_BLOCKS 256
#define BLOCK   512

// ---------------- smem layout (byte offsets) ----------------
#define SA_STRIDE_H 272               // halfs per A row: 256 + 16 pad (word stride 136 = 8 mod 32)
#define SB_STRIDE_H 144               // halfs per B row: 128 + 16 pad (word stride 72  = 8 mod 32)
#define SB_STAGE_B  (64 * SB_STRIDE_H * 2)   // 18432 B per stage
#define B_OFF_F    0                  // s_F[256] floats
#define B_OFF_IDX  1024               // s_idx[256] ints
#define B_OFF_B0   2048               // s_b0[512] floats
#define B_OFF_W1   4096               // s_w1[512] floats
#define B_OFF_A    6144               // s_A: 256 * 544 B = 139264
#define B_OFF_B    (B_OFF_A + TILE_M * SA_STRIDE_H * 2)   // 145408
#define SMEM_BYTES (B_OFF_B + 4 * SB_STAGE_B)             // 219136 B

// ---------------- device scratch ----------------
__device__ __half g_W0H[NTYPE * H1 * DQ];  // W0^T fp16, K-interleaved: [t][j][kperm]
__device__ int    g_idx[N_ATOMS_MAX];
__device__ int    g_part[HIST_BLOCKS][NTYPE];
__device__ int    g_cnt[NTYPE];
__device__ int    g_base[NTYPE];
__device__ int    g_cursor[NTYPE];
__device__ int    g_tileT[MAX_TILES];
__device__ int    g_tileLT[MAX_TILES];
__device__ int    g_ntiles;

// ---------------- helpers ----------------
static __device__ __forceinline__ uint32_t smem_u32(const void* p) {
    uint32_t a;
    asm("{ .reg .u64 t; cvta.to.shared.u64 t, %1; cvt.u32.u64 %0, t; }" : "=r"(a) : "l"(p));
    return a;
}
static __device__ __forceinline__ void cp16(uint32_t dst, const void* src) {
    asm volatile("cp.async.cg.shared.global [%0], [%1], 16;" :: "r"(dst), "l"(src));
}
static __device__ __forceinline__ float tanh_fast(float x) {
    float y;
    asm("tanh.approx.f32 %0, %1;" : "=f"(y) : "f"(x));
    return y;
}
// pack two fp32 -> one u32 of fp16x2 (lo -> lower half)
static __device__ __forceinline__ uint32_t pack_h2(float lo, float hi) {
    uint32_t r;
    asm("cvt.rn.f16x2.f32 %0, %1, %2;" : "=r"(r) : "f"(hi), "f"(lo));
    return r;
}
static __device__ __forceinline__ void mma_f16(float* c, uint32_t a0, uint32_t a1,
                                               uint32_t a2, uint32_t a3,
                                               uint32_t b0, uint32_t b1) {
    asm volatile(
        "mma.sync.aligned.m16n8k16.row.col.f32.f16.f16.f32 "
        "{%0,%1,%2,%3}, {%4,%5,%6,%7}, {%8,%9}, {%0,%1,%2,%3};"
        : "+f"(c[0]), "+f"(c[1]), "+f"(c[2]), "+f"(c[3])
        : "r"(a0), "r"(a1), "r"(a2), "r"(a3), "r"(b0), "r"(b1));
}
// K interleave within each 16-group: order [0,1,8,9, 2,3,10,11, 4,5,12,13, 6,7,14,15]
static __device__ __forceinline__ int kperm16(int k) {
    return (k & ~15) | ((((k & 7) >> 1) << 2) | (((k >> 3) & 1) << 1) | (k & 1));
}

// ---------------- prep kernels ----------------
__global__ void k_hist(const int* __restrict__ Z, int n) {
    __shared__ int h[NTYPE];
    if (threadIdx.x < NTYPE) h[threadIdx.x] = 0;
    __syncthreads();
    for (int i = blockIdx.x * blockDim.x + threadIdx.x; i < n; i += gridDim.x * blockDim.x)
        atomicAdd(&h[Z[i]], 1);
    __syncthreads();
    if (threadIdx.x < NTYPE) g_part[blockIdx.x][threadIdx.x] = h[threadIdx.x];
}

__global__ void k_offsets() {
    __shared__ int cnt[NTYPE];
    __shared__ int ts[NTYPE + 1];
    if (threadIdx.x < NTYPE) {
        int s = 0;
        for (int i = 0; i < HIST_BLOCKS; i++) s += g_part[i][threadIdx.x];
        cnt[threadIdx.x] = s;
        g_cnt[threadIdx.x] = s;
    }
    __syncthreads();
    if (threadIdx.x == 0) {
        int b = 0, ti = 0;
        for (int t = 0; t < NTYPE; t++) {
            g_base[t] = b; g_cursor[t] = b; b += cnt[t];
            ts[t] = ti; ti += (cnt[t] + TILE_M - 1) / TILE_M;
        }
        ts[NTYPE] = ti;
        g_ntiles = ti;
    }
    __syncthreads();
    const int nt = ts[NTYPE];
    for (int ti = threadIdx.x; ti < nt; ti += blockDim.x) {
        int t = 0;
        while (t < NTYPE - 1 && ti >= ts[t + 1]) t++;
        g_tileT[ti] = t;
        g_tileLT[ti] = ti - ts[t];
    }
}

// Fused: blocks [0, nScatterBlocks) do the scatter; the rest do the W0 transpose.
// (Keeps k_gemm as the 4th launch so ncu's fixed capture slot lands on it.)
__global__ void k_scatter_transpose(const int* __restrict__ Z, int n,
                                    const float* __restrict__ W0, int nScatterBlocks) {
    if (blockIdx.x < nScatterBlocks) {
        int i = blockIdx.x * blockDim.x + threadIdx.x;
        if (i >= n) return;  // n multiple of 256 -> warps stay converged
        int z = Z[i];
        int lane = threadIdx.x & 31;
#pragma unroll
        for (int t = 0; t < NTYPE; t++) {
            unsigned m = __ballot_sync(0xffffffffu, z == t);
            if (z == t) {
                int leader = __ffs(m) - 1;
                int rank = __popc(m & ((1u << lane) - 1u));
                int base = 0;
                if (lane == leader) base = atomicAdd(&g_cursor[t], __popc(m));
                base = __shfl_sync(m, base, leader);
                g_idx[base + rank] = i;
            }
        }
    } else {
        // W0 [T][DQ][H1] fp32 -> g_W0H [T][H1][kperm16(DQ)] fp16
        __shared__ float tile[32][33];
        int bid2 = blockIdx.x - nScatterBlocks;     // 512 blocks: 8 x 16 x 4
        int kx = bid2 & 7, jy = (bid2 >> 3) & 15, t = bid2 >> 7;
        int k0 = kx * 32, j0 = jy * 32;
        int x = threadIdx.x & 31, y0 = threadIdx.x >> 5;   // 32 x 8
#pragma unroll
        for (int dy = 0; dy < 32; dy += 8) {
            int k = k0 + y0 + dy, j = j0 + x;
            tile[y0 + dy][x] = W0[((size_t)t * DQ + k) * H1 + j];
        }
        __syncthreads();
#pragma unroll
        for (int dy = 0; dy < 32; dy += 8) {
            int j = j0 + y0 + dy, k = k0 + x;
            g_W0H[((size_t)t * H1 + j) * DQ + kperm16(k)] = __float2half_rn(tile[x][y0 + dy]);
        }
    }
}

// ---------------- main fused GEMM + tanh + dot kernel ----------------
// 16 chunks: ci = ng*2 + kc  (ng = 64-row n-group 0..7, kc = K half 0..1), slot = ci & 3
static __device__ __forceinline__ void load_B_stage(int ci, uint32_t sB_u32,
                                                    const __half* __restrict__ w0h, int tid) {
    const int ng = ci >> 1, kc = ci & 1;
    const uint32_t dst0 = sB_u32 + (ci & 3) * SB_STAGE_B;
#pragma unroll
    for (int o = 0; o < 2; o++) {
        int lin = o * BLOCK + tid;          // 1024 tasks: 64 rows x 16 segs of 16 B
        int row = lin >> 4, seg = lin & 15;
        const __half* src = w0h + (size_t)(ng * 64 + row) * DQ + kc * 128 + seg * 8;
        cp16(dst0 + (row * SB_STRIDE_H + seg * 8) * 2, src);
    }
    asm volatile("cp.async.commit_group;" ::: "memory");
}

__global__ void __launch_bounds__(BLOCK, 1)
k_gemm(const float* __restrict__ q, const float* __restrict__ b0,
       const float* __restrict__ W1, const float* __restrict__ b1v,
       float* __restrict__ out) {
    extern __shared__ char smem[];
    const int tid = threadIdx.x;
    const int wid = tid >> 5, lane = tid & 31;
    const int g = lane >> 2, tig = lane & 3;
    const int warpM = wid >> 2, warpN = wid & 3;   // 4M x 4N warps; each M-warp: 64 rows
    const int bid = blockIdx.x;

    if (bid >= g_ntiles) return;

    const int t = g_tileT[bid], lt = g_tileLT[bid];
    const int cnt = g_cnt[t], base = g_base[t];
    const int row0 = lt * TILE_M;

    float*  s_F   = (float*)(smem + B_OFF_F);
    int*    s_idx = (int*)(smem + B_OFF_IDX);
    float*  s_b0  = (float*)(smem + B_OFF_B0);
    float*  s_w1  = (float*)(smem + B_OFF_W1);
    __half* s_A   = (__half*)(smem + B_OFF_A);
    __half* s_B   = (__half*)(smem + B_OFF_B);

    if (tid < TILE_M) {
        int r = row0 + tid;
        s_idx[tid] = g_idx[base + (r < cnt ? r : row0)];
        s_F[tid] = 0.0f;
    }
    if (tid < H1) {
        s_b0[tid] = b0[t * H1 + tid];
        s_w1[tid] = W1[t * H1 + tid];
    }
    __syncthreads();   // s_idx visible

    const __half* w0h = g_W0H + (size_t)t * H1 * DQ;
    const uint32_t sB_u32 = smem_u32(s_B);

    // pipeline prologue: stages 0, 1, 2 in flight
    load_B_stage(0, sB_u32, w0h, tid);
    load_B_stage(1, sB_u32, w0h, tid);
    load_B_stage(2, sB_u32, w0h, tid);

    // A gather: 256 rows x 16 k-groups = 4096 tasks (8/thread)
#pragma unroll
    for (int o = 0; o < 8; o++) {
        int lin = o * BLOCK + tid;
        int row = lin >> 4, grp = lin & 15;
        const float* src = q + (size_t)s_idx[row] * DQ + grp * 16;
        float v[16];
#pragma unroll
        for (int s = 0; s < 4; s++) {
            const float4 f4 = *(const float4*)(src + s * 4);
            v[s * 4 + 0] = f4.x; v[s * 4 + 1] = f4.y;
            v[s * 4 + 2] = f4.z; v[s * 4 + 3] = f4.w;
        }
        uint32_t w[8];
#pragma unroll
        for (int ww = 0; ww < 8; ww++) {
            const int i_lo = (ww & 1) * 8 + (ww >> 1) * 2;
            w[ww] = pack_h2(v[i_lo], v[i_lo + 1]);
        }
        uint32_t* dst = (uint32_t*)(s_A + row * SA_STRIDE_H + grp * 16);
        *(uint4*)(dst)     = make_uint4(w[0], w[1], w[2], w[3]);
        *(uint4*)(dst + 4) = make_uint4(w[4], w[5], w[6], w[7]);
    }

    const float b1s = b1v[0];

#pragma unroll 1
    for (int ng = 0; ng < 8; ng++) {            // 64-col n-groups
        float acc[4][2][4];
#pragma unroll
        for (int i = 0; i < 4; i++)
#pragma unroll
            for (int j = 0; j < 2; j++)
#pragma unroll
                for (int c = 0; c < 4; c++) acc[i][j][c] = 0.0f;

#pragma unroll 1
        for (int kc = 0; kc < 2; kc++) {
            const int ci = ng * 2 + kc;
            if (ci < 14)       asm volatile("cp.async.wait_group 2;" ::: "memory");
            else if (ci == 14) asm volatile("cp.async.wait_group 1;" ::: "memory");
            else               asm volatile("cp.async.wait_group 0;" ::: "memory");
            __syncthreads();   // stage ci visible; all warps done with stage ci-1

            if (ci + 3 < 16) load_B_stage(ci + 3, sB_u32, w0h, tid);

            const __half* Bs = s_B + (ci & 3) * (SB_STAGE_B / 2);
#pragma unroll
            for (int p = 0; p < 8; p++) {        // k16 steps within this K-half
                const int kofs = kc * 128 + p * 16;
                uint2 a[4][2];
#pragma unroll
                for (int i = 0; i < 4; i++) {
                    const __half* Ar = s_A + (warpM * 64 + i * 16 + g) * SA_STRIDE_H + kofs + tig * 4;
                    a[i][0] = *(const uint2*)(Ar);                     // {a0, a2} row r
                    a[i][1] = *(const uint2*)(Ar + 8 * SA_STRIDE_H);   // {a1, a3} row r+8
                }
#pragma unroll
                for (int j = 0; j < 2; j++) {
                    const int n = warpN * 16 + j * 8 + g;
                    const uint2 bv = *(const uint2*)(Bs + n * SB_STRIDE_H + p * 16 + tig * 4);
#pragma unroll
                    for (int i = 0; i < 4; i++)
                        mma_f16(acc[i][j], a[i][0].x, a[i][1].x, a[i][0].y, a[i][1].y, bv.x, bv.y);
                }
            }
        }

        // ---- epilogue for this 64-col group: tanh(h + b0) * W1, reduce over n ----
        float fa[4][2];
#pragma unroll
        for (int i = 0; i < 4; i++) { fa[i][0] = 0.0f; fa[i][1] = 0.0f; }
#pragma unroll
        for (int i = 0; i < 4; i++)
#pragma unroll
            for (int j = 0; j < 2; j++)
#pragma unroll
                for (int c = 0; c < 4; c++) {
                    const int colg = ng * 64 + warpN * 16 + j * 8 + tig * 2 + (c & 1);
                    const float h = tanh_fast(acc[i][j][c] + s_b0[colg]);
                    fa[i][c >> 1] = fmaf(h, s_w1[colg], fa[i][c >> 1]);
                }
#pragma unroll
        for (int i = 0; i < 4; i++)
#pragma unroll
            for (int hh = 0; hh < 2; hh++) {
                fa[i][hh] += __shfl_xor_sync(0xffffffffu, fa[i][hh], 1);
                fa[i][hh] += __shfl_xor_sync(0xffffffffu, fa[i][hh], 2);
            }
        if (tig == 0) {
#pragma unroll
            for (int i = 0; i < 4; i++)
#pragma unroll
                for (int hh = 0; hh < 2; hh++) {
                    const int m = warpM * 64 + i * 16 + hh * 8 + g;
                    atomicAdd(&s_F[m], fa[i][hh]);
                }
        }
    }

    __syncthreads();
    if (tid < TILE_M) {
        if (row0 + tid < cnt) out[s_idx[tid]] = s_F[tid] + b1s;
    }
}

// ---------------- launch ----------------
extern "C" void kernel_launch(void* const* d_in, const int* in_sizes, int n_in,
                              void* d_out, int out_size) {
    const float* q  = (const float*)d_in[0];
    const int*   Z  = (const int*)d_in[1];
    const float* W0 = (const float*)d_in[2];
    const float* b0 = (const float*)d_in[3];
    const float* W1 = (const float*)d_in[4];
    const float* b1 = (const float*)d_in[5];
    float* out = (float*)d_out;
    int n = in_sizes[1];

    const int nScatterBlocks = (n + 255) / 256;
    k_hist<<<HIST_BLOCKS, 256>>>(Z, n);
    k_offsets<<<1, 256>>>();
    k_scatter_transpose<<<nScatterBlocks + 512, 256>>>(Z, n, W0, nScatterBlocks);

    cudaFuncSetAttribute(k_gemm, cudaFuncAttributeMaxDynamicSharedMemorySize, SMEM_BYTES);
    k_gemm<<<MAX_TILES, BLOCK, SMEM_BYTES>>>(q, b0, W1, b1, out);
}

// round 8
// speedup vs baseline: 2.1368x; 1.2288x over previous
#include <cuda_runtime.h>
#include <cuda_fp16.h>
#include <cstdint>

// ---------------- problem constants ----------------
#define N_ATOMS_MAX 131072
#define DQ      256
#define H1      512
#define NTYPE   4
#define TILE_M  256
#define MAX_TILES (N_ATOMS_MAX / TILE_M + NTYPE)  // 516
#define BLOCK   512

// ---------------- smem layout (byte offsets) ----------------
// A: [blk16 0..15][grp 0..15][lane 0..31] x 16 B  (fragment-order, lane^grp&7 swizz)
// B: 4 stages x [blkn 0..3][p 0..7][lane 0..31] x 16 B
#define B_OFF_F    0                    // s_F[256] floats
#define B_OFF_IDX  1024                 // s_idx[256] ints
#define B_OFF_B0   2048                 // s_b0[512] floats
#define B_OFF_W1   4096                 // s_w1[512] floats
#define B_OFF_A    6144                 // 128 KB
#define B_OFF_B    (B_OFF_A + 131072)   // 137216; 4 x 16 KB stages
#define SMEM_BYTES (B_OFF_B + 4 * 16384)   // 202752 B

// ---------------- device scratch ----------------
__device__ __half g_W0H[NTYPE * H1 * DQ];   // W0^T fp16, fragment-order layout
__device__ int    g_idx[NTYPE * N_ATOMS_MAX];  // per-type regions
__device__ int    g_cnt[NTYPE];
__device__ int    g_tileT[MAX_TILES];
__device__ int    g_tileLT[MAX_TILES];
__device__ int    g_ntiles;

// ---------------- helpers ----------------
static __device__ __forceinline__ uint32_t smem_u32(const void* p) {
    uint32_t a;
    asm("{ .reg .u64 t; cvta.to.shared.u64 t, %1; cvt.u32.u64 %0, t; }" : "=r"(a) : "l"(p));
    return a;
}
static __device__ __forceinline__ void cp16(uint32_t dst, const void* src) {
    asm volatile("cp.async.cg.shared.global [%0], [%1], 16;" :: "r"(dst), "l"(src));
}
static __device__ __forceinline__ float tanh_fast(float x) {
    float y;
    asm("tanh.approx.f32 %0, %1;" : "=f"(y) : "f"(x));
    return y;
}
static __device__ __forceinline__ uint32_t pack_h2(float lo, float hi) {
    uint32_t r;
    asm("cvt.rn.f16x2.f32 %0, %1, %2;" : "=r"(r) : "f"(hi), "f"(lo));
    return r;
}
static __device__ __forceinline__ void mma_f16(float* c, uint32_t a0, uint32_t a1,
                                               uint32_t a2, uint32_t a3,
                                               uint32_t b0, uint32_t b1) {
    asm volatile(
        "mma.sync.aligned.m16n8k16.row.col.f32.f16.f16.f32 "
        "{%0,%1,%2,%3}, {%4,%5,%6,%7}, {%8,%9}, {%0,%1,%2,%3};"
        : "+f"(c[0]), "+f"(c[1]), "+f"(c[2]), "+f"(c[3])
        : "r"(a0), "r"(a1), "r"(a2), "r"(a3), "r"(b0), "r"(b1));
}

// ---------------- prep 1: init counters + W0 transpose into fragment-order ----
// grid 512 x 256 thr. Blocks map (kx 0..7, jy 0..15, t 0..3).
__global__ void k_init_transpose(const float* __restrict__ W0) {
    if (blockIdx.x == 0 && threadIdx.x < NTYPE) g_cnt[threadIdx.x] = 0;
    __shared__ float tile[32][33];
    const int bid = blockIdx.x;
    const int kx = bid & 7, jy = (bid >> 3) & 15, t = bid >> 7;
    const int k0 = kx * 32, j0 = jy * 32;
    const int x = threadIdx.x & 31, y0 = threadIdx.x >> 5;   // 32 x 8
#pragma unroll
    for (int dy = 0; dy < 32; dy += 8) {
        int k = k0 + y0 + dy, j = j0 + x;
        tile[y0 + dy][x] = W0[((size_t)t * DQ + k) * H1 + j];
    }
    __syncthreads();
#pragma unroll
    for (int dy = 0; dy < 32; dy += 8) {
        const int j = j0 + y0 + dy;     // H1 index (n)
        const int k = k0 + x;           // DQ index
        const int ng = j >> 6, r6 = j & 63;
        const int blkn = r6 >> 4, rb = r6 & 15;
        const int jj = rb >> 3, g = rb & 7;
        const int kc = k >> 7, k7 = k & 127;
        const int p = k7 >> 4, ki = k7 & 15;
        const int tg = (ki >> 1) & 3;
        const int posq = ((ki >> 3) << 1) | (ki & 1);
        const int lane = (g * 4 + tg) ^ p;   // bake read swizzle
        const int halfIdx = ((((ng * 2 + kc) * 4 + blkn) * 8 + p) << 8) + lane * 8 + jj * 4 + posq;
        g_W0H[(size_t)t * (H1 * DQ) + halfIdx] = __float2half_rn(tile[x][y0 + dy]);
    }
}

// ---------------- prep 2: scatter with block-aggregated atomics ----------------
__global__ void k_scatter(const int* __restrict__ Z, int n) {
    __shared__ int wcnt[8][NTYPE];
    __shared__ int wbase[8][NTYPE];
    __shared__ int blkbase[NTYPE];
    const int i = blockIdx.x * blockDim.x + threadIdx.x;
    const int lane = threadIdx.x & 31, w = threadIdx.x >> 5;
    int z = -1, rank = 0;
    if (i < n) {
        z = Z[i];
#pragma unroll
        for (int t = 0; t < NTYPE; t++) {
            unsigned m = __ballot_sync(0xffffffffu, z == t);
            if (lane == 0) wcnt[w][t] = __popc(m);
            if (z == t) rank = __popc(m & ((1u << lane) - 1u));
        }
    } else if (lane == 0) {
#pragma unroll
        for (int t = 0; t < NTYPE; t++) wcnt[w][t] = 0;
    }
    __syncthreads();
    if (threadIdx.x < NTYPE) {
        const int t = threadIdx.x;
        int s = 0;
#pragma unroll
        for (int w2 = 0; w2 < 8; w2++) { wbase[w2][t] = s; s += wcnt[w2][t]; }
        blkbase[t] = atomicAdd(&g_cnt[t], s);
    }
    __syncthreads();
    if (z >= 0) g_idx[z * N_ATOMS_MAX + blkbase[z] + wbase[w][z] + rank] = i;
}

// ---------------- prep 3: tile table ----------------
__global__ void k_tiles() {
    __shared__ int ts[NTYPE + 1];
    if (threadIdx.x == 0) {
        int ti = 0;
        for (int t = 0; t < NTYPE; t++) {
            ts[t] = ti;
            ti += (g_cnt[t] + TILE_M - 1) / TILE_M;
        }
        ts[NTYPE] = ti;
        g_ntiles = ti;
    }
    __syncthreads();
    const int nt = ts[NTYPE];
    for (int ti = threadIdx.x; ti < nt; ti += blockDim.x) {
        int t = 0;
        while (t < NTYPE - 1 && ti >= ts[t + 1]) t++;
        g_tileT[ti] = t;
        g_tileLT[ti] = ti - ts[t];
    }
}

// ---------------- main fused GEMM + tanh + dot kernel ----------------
// 16 chunks: ci = ng*2 + kc; B stage = 16 KB contiguous slice ci of g_W0H[t]
static __device__ __forceinline__ void load_B_stage(int ci, uint32_t sB_u32,
                                                    const __half* __restrict__ w0h, int tid) {
    const uint32_t dst0 = sB_u32 + (ci & 3) * 16384;
    const __half* src0 = w0h + ci * 8192;
#pragma unroll
    for (int o = 0; o < 2; o++) {
        const int lin = o * BLOCK + tid;   // 1024 x 16 B
        cp16(dst0 + lin * 16, src0 + lin * 8);
    }
    asm volatile("cp.async.commit_group;" ::: "memory");
}

__global__ void __launch_bounds__(BLOCK, 1)
k_gemm(const float* __restrict__ q, const float* __restrict__ b0,
       const float* __restrict__ W1, const float* __restrict__ b1v,
       float* __restrict__ out) {
    extern __shared__ char smem[];
    const int tid = threadIdx.x;
    const int wid = tid >> 5, lane = tid & 31;
    const int g = lane >> 2, tig = lane & 3;
    const int warpM = wid >> 1, warpN = wid & 1;   // 8M x 2N; warp tile 32 rows x 32 cols
    const int bid = blockIdx.x;

    if (bid >= g_ntiles) return;

    const int t = g_tileT[bid], lt = g_tileLT[bid];
    const int cnt = g_cnt[t];
    const int row0 = lt * TILE_M;

    float*  s_F   = (float*)(smem + B_OFF_F);
    int*    s_idx = (int*)(smem + B_OFF_IDX);
    float*  s_b0  = (float*)(smem + B_OFF_B0);
    float*  s_w1  = (float*)(smem + B_OFF_W1);
    char*   s_A   = smem + B_OFF_A;
    char*   s_B   = smem + B_OFF_B;

    if (tid < TILE_M) {
        int r = row0 + tid;
        s_idx[tid] = g_idx[t * N_ATOMS_MAX + (r < cnt ? r : row0)];
        s_F[tid] = 0.0f;
    }
    s_b0[tid] = b0[t * H1 + tid];
    s_w1[tid] = W1[t * H1 + tid];
    __syncthreads();   // s_idx visible

    const __half* w0h = g_W0H + (size_t)t * (H1 * DQ);
    const uint32_t sB_u32 = smem_u32(s_B);

    // prologue: stages 0,1,2 in flight
    load_B_stage(0, sB_u32, w0h, tid);
    load_B_stage(1, sB_u32, w0h, tid);
    load_B_stage(2, sB_u32, w0h, tid);

    // A gather: 256 rows x 16 k16-groups; fragment-order store with lane^grp swizzle
#pragma unroll
    for (int o = 0; o < 8; o++) {
        const int lin = o * BLOCK + tid;        // 4096 tasks
        const int grp = lin & 15, row = lin >> 4;
        const float* src = q + (size_t)s_idx[row] * DQ + grp * 16;
        float v[16];
#pragma unroll
        for (int s = 0; s < 4; s++) {
            const float4 f4 = *(const float4*)(src + s * 4);
            v[s * 4 + 0] = f4.x; v[s * 4 + 1] = f4.y;
            v[s * 4 + 2] = f4.z; v[s * 4 + 3] = f4.w;
        }
        const int blk = row >> 4, half = (row >> 3) & 1, gg = row & 7;
        char* dbase = s_A + ((blk * 16 + grp) << 9) + half * 8;
        const int sw = grp & 7;
#pragma unroll
        for (int tt = 0; tt < 4; tt++) {
            uint2 pr;
            pr.x = pack_h2(v[tt * 2],     v[tt * 2 + 1]);
            pr.y = pack_h2(v[tt * 2 + 8], v[tt * 2 + 9]);
            *(uint2*)(dbase + (((gg * 4 + tt) ^ sw) << 4)) = pr;
        }
    }

    const float b1s = b1v[0];

#pragma unroll 1
    for (int ng = 0; ng < 8; ng++) {            // 64-col n-groups
        float acc[2][4][4];
#pragma unroll
        for (int i = 0; i < 2; i++)
#pragma unroll
            for (int j = 0; j < 4; j++)
#pragma unroll
                for (int c = 0; c < 4; c++) acc[i][j][c] = 0.0f;

#pragma unroll 1
        for (int kc = 0; kc < 2; kc++) {
            const int ci = ng * 2 + kc;
            if (ci < 14)       asm volatile("cp.async.wait_group 2;" ::: "memory");
            else if (ci == 14) asm volatile("cp.async.wait_group 1;" ::: "memory");
            else               asm volatile("cp.async.wait_group 0;" ::: "memory");
            __syncthreads();   // stage ci visible; all warps done with stage ci-1

            if (ci + 3 < 16) load_B_stage(ci + 3, sB_u32, w0h, tid);

            const char* As0 = s_A + ((warpM * 2 + 0) * 16 + kc * 8) * 512;
            const char* As1 = s_A + ((warpM * 2 + 1) * 16 + kc * 8) * 512;
            const char* Bs0 = s_B + (ci & 3) * 16384 + ((warpN * 2 + 0) * 8) * 512;
            const char* Bs1 = s_B + (ci & 3) * 16384 + ((warpN * 2 + 1) * 8) * 512;
#pragma unroll
            for (int p = 0; p < 8; p++) {
                const int lsw = (lane ^ p) << 4;
                const uint4 A0 = *(const uint4*)(As0 + p * 512 + lsw);
                const uint4 A1 = *(const uint4*)(As1 + p * 512 + lsw);
                const uint4 B0 = *(const uint4*)(Bs0 + p * 512 + lsw);
                const uint4 B1 = *(const uint4*)(Bs1 + p * 512 + lsw);
                // A uint4: {a0, a2, a1, a3}; B uint4: {b0_j0, b1_j0, b0_j1, b1_j1}
                mma_f16(acc[0][0], A0.x, A0.z, A0.y, A0.w, B0.x, B0.y);
                mma_f16(acc[0][1], A0.x, A0.z, A0.y, A0.w, B0.z, B0.w);
                mma_f16(acc[0][2], A0.x, A0.z, A0.y, A0.w, B1.x, B1.y);
                mma_f16(acc[0][3], A0.x, A0.z, A0.y, A0.w, B1.z, B1.w);
                mma_f16(acc[1][0], A1.x, A1.z, A1.y, A1.w, B0.x, B0.y);
                mma_f16(acc[1][1], A1.x, A1.z, A1.y, A1.w, B0.z, B0.w);
                mma_f16(acc[1][2], A1.x, A1.z, A1.y, A1.w, B1.x, B1.y);
                mma_f16(acc[1][3], A1.x, A1.z, A1.y, A1.w, B1.z, B1.w);
            }
        }

        // ---- epilogue: tanh(h + b0) * W1, reduce over 64 cols ----
        float fa[2][2];
        fa[0][0] = fa[0][1] = fa[1][0] = fa[1][1] = 0.0f;
#pragma unroll
        for (int i = 0; i < 2; i++)
#pragma unroll
            for (int j = 0; j < 4; j++)
#pragma unroll
                for (int c = 0; c < 4; c++) {
                    const int colg = ng * 64 + warpN * 32 + j * 8 + tig * 2 + (c & 1);
                    const float h = tanh_fast(acc[i][j][c] + s_b0[colg]);
                    fa[i][c >> 1] = fmaf(h, s_w1[colg], fa[i][c >> 1]);
                }
#pragma unroll
        for (int i = 0; i < 2; i++)
#pragma unroll
            for (int hh = 0; hh < 2; hh++) {
                fa[i][hh] += __shfl_xor_sync(0xffffffffu, fa[i][hh], 1);
                fa[i][hh] += __shfl_xor_sync(0xffffffffu, fa[i][hh], 2);
            }
        if (tig == 0) {
#pragma unroll
            for (int i = 0; i < 2; i++)
#pragma unroll
                for (int hh = 0; hh < 2; hh++) {
                    const int m = warpM * 32 + i * 16 + hh * 8 + g;
                    atomicAdd(&s_F[m], fa[i][hh]);
                }
        }
    }

    __syncthreads();
    if (tid < TILE_M) {
        if (row0 + tid < cnt) out[s_idx[tid]] = s_F[tid] + b1s;
    }
}

// ---------------- launch ----------------
extern "C" void kernel_launch(void* const* d_in, const int* in_sizes, int n_in,
                              void* d_out, int out_size) {
    const float* q  = (const float*)d_in[0];
    const int*   Z  = (const int*)d_in[1];
    const float* W0 = (const float*)d_in[2];
    const float* b0 = (const float*)d_in[3];
    const float* W1 = (const float*)d_in[4];
    const float* b1 = (const float*)d_in[5];
    float* out = (float*)d_out;
    int n = in_sizes[1];

    k_init_transpose<<<512, 256>>>(W0);
    k_scatter<<<(n + 255) / 256, 256>>>(Z, n);
    k_tiles<<<1, 256>>>();

    cudaFuncSetAttribute(k_gemm, cudaFuncAttributeMaxDynamicSharedMemorySize, SMEM_BYTES);
    k_gemm<<<MAX_TILES, BLOCK, SMEM_BYTES>>>(q, b0, W1, b1, out);
}

// round 9
// speedup vs baseline: 2.2562x; 1.0559x over previous
#include <cuda_runtime.h>
#include <cuda_fp16.h>
#include <cstdint>

// ---------------- problem constants ----------------
#define N_ATOMS_MAX 131072
#define DQ      256
#define H1      512
#define NTYPE   4
#define TILE_M  256
#define MAX_TILES (N_ATOMS_MAX / TILE_M + NTYPE)  // 516
#define BLOCK   512

// ---------------- smem layout (byte offsets) ----------------
// A: [blk16 0..15][grp 0..15][lane 0..31] x 16 B   (fragment-order, lane^(grp&7) swizzle)
// B: 4 stages x [blkn 0..7][p 0..3][lane 0..31] x 16 B  (chunk = 128 n x 64 k)
#define B_OFF_F    0                    // s_F[256] floats
#define B_OFF_IDX  1024                 // s_idx[256] ints
#define B_OFF_B0   2048                 // s_b0[512] floats
#define B_OFF_W1   4096                 // s_w1[512] floats
#define B_OFF_A    6144                 // 128 KB
#define B_OFF_B    (B_OFF_A + 131072)   // 137216; 4 x 16 KB stages
#define SMEM_BYTES (B_OFF_B + 4 * 16384)   // 202752 B

// ---------------- device scratch ----------------
__device__ __half g_W0H[NTYPE * H1 * DQ];      // W0^T fp16, fragment-order layout
__device__ int    g_idx[NTYPE * N_ATOMS_MAX];  // per-type regions
__device__ int    g_cnt[NTYPE];
__device__ int    g_tileT[MAX_TILES];
__device__ int    g_tileLT[MAX_TILES];
__device__ int    g_ntiles;

// ---------------- helpers ----------------
static __device__ __forceinline__ uint32_t smem_u32(const void* p) {
    uint32_t a;
    asm("{ .reg .u64 t; cvta.to.shared.u64 t, %1; cvt.u32.u64 %0, t; }" : "=r"(a) : "l"(p));
    return a;
}
static __device__ __forceinline__ void cp16(uint32_t dst, const void* src) {
    asm volatile("cp.async.cg.shared.global [%0], [%1], 16;" :: "r"(dst), "l"(src));
}
static __device__ __forceinline__ float tanh_fast(float x) {
    float y;
    asm("tanh.approx.f32 %0, %1;" : "=f"(y) : "f"(x));
    return y;
}
static __device__ __forceinline__ uint32_t pack_h2(float lo, float hi) {
    uint32_t r;
    asm("cvt.rn.f16x2.f32 %0, %1, %2;" : "=r"(r) : "f"(hi), "f"(lo));
    return r;
}
static __device__ __forceinline__ void mma_f16(float* c, uint32_t a0, uint32_t a1,
                                               uint32_t a2, uint32_t a3,
                                               uint32_t b0, uint32_t b1) {
    asm volatile(
        "mma.sync.aligned.m16n8k16.row.col.f32.f16.f16.f32 "
        "{%0,%1,%2,%3}, {%4,%5,%6,%7}, {%8,%9}, {%0,%1,%2,%3};"
        : "+f"(c[0]), "+f"(c[1]), "+f"(c[2]), "+f"(c[3])
        : "r"(a0), "r"(a1), "r"(a2), "r"(a3), "r"(b0), "r"(b1));
}

// ---------------- prep 1: init counters + W0 transpose into fragment-order ----
// grid 512 x 256 thr. Blocks map (kx 0..7, jy 0..15, t 0..3).
__global__ void k_init_transpose(const float* __restrict__ W0) {
    if (blockIdx.x == 0 && threadIdx.x < NTYPE) g_cnt[threadIdx.x] = 0;
    __shared__ float tile[32][33];
    const int bid = blockIdx.x;
    const int kx = bid & 7, jy = (bid >> 3) & 15, t = bid >> 7;
    const int k0 = kx * 32, j0 = jy * 32;
    const int x = threadIdx.x & 31, y0 = threadIdx.x >> 5;   // 32 x 8
#pragma unroll
    for (int dy = 0; dy < 32; dy += 8) {
        int k = k0 + y0 + dy, j = j0 + x;
        tile[y0 + dy][x] = W0[((size_t)t * DQ + k) * H1 + j];
    }
    __syncthreads();
#pragma unroll
    for (int dy = 0; dy < 32; dy += 8) {
        const int j = j0 + y0 + dy;     // H1 index (n)
        const int k = k0 + x;           // DQ index
        const int ng   = j >> 7;         // 128-col n-group
        const int blkn = (j >> 4) & 7;   // 16-col block within group
        const int rb   = j & 15;
        const int jj = rb >> 3, g = rb & 7;
        const int kc = k >> 6;           // 64-k chunk
        const int p  = (k >> 4) & 3;     // k16 step within chunk
        const int ki = k & 15;
        const int tg = (ki >> 1) & 3;
        const int posq = ((ki >> 3) << 1) | (ki & 1);
        const int lane = (g * 4 + tg) ^ p;   // bake read swizzle
        const int ci = ng * 4 + kc;
        const int halfIdx = (((ci * 8 + blkn) * 4 + p) << 8) + lane * 8 + jj * 4 + posq;
        g_W0H[(size_t)t * (H1 * DQ) + halfIdx] = __float2half_rn(tile[x][y0 + dy]);
    }
}

// ---------------- prep 2: scatter with block-aggregated atomics ----------------
__global__ void k_scatter(const int* __restrict__ Z, int n) {
    __shared__ int wcnt[8][NTYPE];
    __shared__ int wbase[8][NTYPE];
    __shared__ int blkbase[NTYPE];
    const int i = blockIdx.x * blockDim.x + threadIdx.x;
    const int lane = threadIdx.x & 31, w = threadIdx.x >> 5;
    int z = -1, rank = 0;
    if (i < n) {
        z = Z[i];
#pragma unroll
        for (int t = 0; t < NTYPE; t++) {
            unsigned m = __ballot_sync(0xffffffffu, z == t);
            if (lane == 0) wcnt[w][t] = __popc(m);
            if (z == t) rank = __popc(m & ((1u << lane) - 1u));
        }
    } else if (lane == 0) {
#pragma unroll
        for (int t = 0; t < NTYPE; t++) wcnt[w][t] = 0;
    }
    __syncthreads();
    if (threadIdx.x < NTYPE) {
        const int t = threadIdx.x;
        int s = 0;
#pragma unroll
        for (int w2 = 0; w2 < 8; w2++) { wbase[w2][t] = s; s += wcnt[w2][t]; }
        blkbase[t] = atomicAdd(&g_cnt[t], s);
    }
    __syncthreads();
    if (z >= 0) g_idx[z * N_ATOMS_MAX + blkbase[z] + wbase[w][z] + rank] = i;
}

// ---------------- prep 3: tile table ----------------
__global__ void k_tiles() {
    __shared__ int ts[NTYPE + 1];
    if (threadIdx.x == 0) {
        int ti = 0;
        for (int t = 0; t < NTYPE; t++) {
            ts[t] = ti;
            ti += (g_cnt[t] + TILE_M - 1) / TILE_M;
        }
        ts[NTYPE] = ti;
        g_ntiles = ti;
    }
    __syncthreads();
    const int nt = ts[NTYPE];
    for (int ti = threadIdx.x; ti < nt; ti += blockDim.x) {
        int t = 0;
        while (t < NTYPE - 1 && ti >= ts[t + 1]) t++;
        g_tileT[ti] = t;
        g_tileLT[ti] = ti - ts[t];
    }
}

// ---------------- main fused GEMM + tanh + dot kernel ----------------
// 16 chunks: ci = ng*4 + kc; stage = contiguous 16 KB slice ci of g_W0H[t]
static __device__ __forceinline__ void load_B_stage(int ci, uint32_t sB_u32,
                                                    const __half* __restrict__ w0h, int tid) {
    const uint32_t dst0 = sB_u32 + (ci & 3) * 16384;
    const __half* src0 = w0h + ci * 8192;
#pragma unroll
    for (int o = 0; o < 2; o++) {
        const int lin = o * BLOCK + tid;   // 1024 x 16 B
        cp16(dst0 + lin * 16, src0 + lin * 8);
    }
    asm volatile("cp.async.commit_group;" ::: "memory");
}

__global__ void __launch_bounds__(BLOCK, 1)
k_gemm(const float* __restrict__ q, const float* __restrict__ b0,
       const float* __restrict__ W1, const float* __restrict__ b1v,
       float* __restrict__ out) {
    extern __shared__ char smem[];
    const int tid = threadIdx.x;
    const int wid = tid >> 5, lane = tid & 31;
    const int g = lane >> 2, tig = lane & 3;
    const int warpM = wid >> 2, warpN = wid & 3;   // 4M x 4N; warp tile 64 rows x 32 cols
    const int bid = blockIdx.x;

    if (bid >= g_ntiles) return;

    const int t = g_tileT[bid], lt = g_tileLT[bid];
    const int cnt = g_cnt[t];
    const int row0 = lt * TILE_M;

    float*  s_F   = (float*)(smem + B_OFF_F);
    int*    s_idx = (int*)(smem + B_OFF_IDX);
    float*  s_b0  = (float*)(smem + B_OFF_B0);
    float*  s_w1  = (float*)(smem + B_OFF_W1);
    char*   s_A   = smem + B_OFF_A;
    char*   s_B   = smem + B_OFF_B;

    if (tid < TILE_M) {
        int r = row0 + tid;
        s_idx[tid] = g_idx[t * N_ATOMS_MAX + (r < cnt ? r : row0)];
        s_F[tid] = 0.0f;
    }
    s_b0[tid] = b0[t * H1 + tid];
    s_w1[tid] = W1[t * H1 + tid];
    __syncthreads();   // s_idx visible

    const __half* w0h = g_W0H + (size_t)t * (H1 * DQ);
    const uint32_t sB_u32 = smem_u32(s_B);

    // prologue: stages 0,1,2 in flight
    load_B_stage(0, sB_u32, w0h, tid);
    load_B_stage(1, sB_u32, w0h, tid);
    load_B_stage(2, sB_u32, w0h, tid);

    // A gather: 256 rows x 16 k16-groups; fragment-order store with lane^(grp&7) swizzle
#pragma unroll
    for (int o = 0; o < 8; o++) {
        const int lin = o * BLOCK + tid;        // 4096 tasks
        const int grp = lin & 15, row = lin >> 4;
        const float* src = q + (size_t)s_idx[row] * DQ + grp * 16;
        float v[16];
#pragma unroll
        for (int s = 0; s < 4; s++) {
            const float4 f4 = *(const float4*)(src + s * 4);
            v[s * 4 + 0] = f4.x; v[s * 4 + 1] = f4.y;
            v[s * 4 + 2] = f4.z; v[s * 4 + 3] = f4.w;
        }
        const int blk = row >> 4, half = (row >> 3) & 1, gg = row & 7;
        char* dbase = s_A + ((blk * 16 + grp) << 9) + half * 8;
        const int sw = grp & 7;
#pragma unroll
        for (int tt = 0; tt < 4; tt++) {
            uint2 pr;
            pr.x = pack_h2(v[tt * 2],     v[tt * 2 + 1]);
            pr.y = pack_h2(v[tt * 2 + 8], v[tt * 2 + 9]);
            *(uint2*)(dbase + (((gg * 4 + tt) ^ sw) << 4)) = pr;
        }
    }

    const float b1s = b1v[0];

#pragma unroll 1
    for (int ng = 0; ng < 4; ng++) {            // 128-col n-groups
        float acc[4][4][4];                     // [i: 16-row blk][f = bb*2+jj][c]
#pragma unroll
        for (int i = 0; i < 4; i++)
#pragma unroll
            for (int f = 0; f < 4; f++)
#pragma unroll
                for (int c = 0; c < 4; c++) acc[i][f][c] = 0.0f;

#pragma unroll 1
        for (int kc = 0; kc < 4; kc++) {
            const int ci = ng * 4 + kc;
            if (ci < 14)       asm volatile("cp.async.wait_group 2;" ::: "memory");
            else if (ci == 14) asm volatile("cp.async.wait_group 1;" ::: "memory");
            else               asm volatile("cp.async.wait_group 0;" ::: "memory");
            __syncthreads();   // stage ci visible; all warps done with stage ci-1

            if (ci + 3 < 16) load_B_stage(ci + 3, sB_u32, w0h, tid);

            const char* As = s_A + (warpM * 4 * 16 + kc * 4) * 512;   // + (i*16 + p)*512
            const char* Bs = s_B + (ci & 3) * 16384 + (warpN * 2 * 4) * 512;  // + (bb*4+p)*512
#pragma unroll
            for (int p = 0; p < 4; p++) {
                const int swA = (lane ^ (((kc & 1) << 2) | p)) << 4;
                const int swB = (lane ^ p) << 4;
                uint4 A[4];
#pragma unroll
                for (int i = 0; i < 4; i++)
                    A[i] = *(const uint4*)(As + (i * 16 + p) * 512 + swA);
                const uint4 B0 = *(const uint4*)(Bs + p * 512 + swB);
                const uint4 B1 = *(const uint4*)(Bs + (4 + p) * 512 + swB);
                // A uint4: {a0, a2, a1, a3}; B uint4: {b0_j0, b1_j0, b0_j1, b1_j1}
#pragma unroll
                for (int i = 0; i < 4; i++) {
                    mma_f16(acc[i][0], A[i].x, A[i].z, A[i].y, A[i].w, B0.x, B0.y);
                    mma_f16(acc[i][1], A[i].x, A[i].z, A[i].y, A[i].w, B0.z, B0.w);
                    mma_f16(acc[i][2], A[i].x, A[i].z, A[i].y, A[i].w, B1.x, B1.y);
                    mma_f16(acc[i][3], A[i].x, A[i].z, A[i].y, A[i].w, B1.z, B1.w);
                }
            }
        }

        // ---- epilogue: tanh(h + b0) * W1, reduce over this 128-col group ----
        float fa[4][2];
#pragma unroll
        for (int i = 0; i < 4; i++) { fa[i][0] = 0.0f; fa[i][1] = 0.0f; }
#pragma unroll
        for (int i = 0; i < 4; i++)
#pragma unroll
            for (int f = 0; f < 4; f++) {
                const int bb = f >> 1, jj = f & 1;
#pragma unroll
                for (int c = 0; c < 4; c++) {
                    const int colg = ng * 128 + warpN * 32 + bb * 16 + jj * 8 + tig * 2 + (c & 1);
                    const float h = tanh_fast(acc[i][f][c] + s_b0[colg]);
                    fa[i][c >> 1] = fmaf(h, s_w1[colg], fa[i][c >> 1]);
                }
            }
#pragma unroll
        for (int i = 0; i < 4; i++)
#pragma unroll
            for (int hh = 0; hh < 2; hh++) {
                fa[i][hh] += __shfl_xor_sync(0xffffffffu, fa[i][hh], 1);
                fa[i][hh] += __shfl_xor_sync(0xffffffffu, fa[i][hh], 2);
            }
        if (tig == 0) {
#pragma unroll
            for (int i = 0; i < 4; i++)
#pragma unroll
                for (int hh = 0; hh < 2; hh++) {
                    const int m = warpM * 64 + i * 16 + hh * 8 + g;
                    atomicAdd(&s_F[m], fa[i][hh]);
                }
        }
    }

    __syncthreads();
    if (tid < TILE_M) {
        if (row0 + tid < cnt) out[s_idx[tid]] = s_F[tid] + b1s;
    }
}

// ---------------- launch ----------------
extern "C" void kernel_launch(void* const* d_in, const int* in_sizes, int n_in,
                              void* d_out, int out_size) {
    const float* q  = (const float*)d_in[0];
    const int*   Z  = (const int*)d_in[1];
    const float* W0 = (const float*)d_in[2];
    const float* b0 = (const float*)d_in[3];
    const float* W1 = (const float*)d_in[4];
    const float* b1 = (const float*)d_in[5];
    float* out = (float*)d_out;
    int n = in_sizes[1];

    k_init_transpose<<<512, 256>>>(W0);
    k_scatter<<<(n + 255) / 256, 256>>>(Z, n);
    k_tiles<<<1, 256>>>();

    cudaFuncSetAttribute(k_gemm, cudaFuncAttributeMaxDynamicSharedMemorySize, SMEM_BYTES);
    k_gemm<<<MAX_TILES, BLOCK, SMEM_BYTES>>>(q, b0, W1, b1, out);
}

// round 10
// speedup vs baseline: 2.4618x; 1.0911x over previous
#include <cuda_runtime.h>
#include <cuda_fp16.h>
#include <cstdint>

// ---------------- problem constants ----------------
#define N_ATOMS_MAX 131072
#define DQ      256
#define H1      512
#define NTYPE   4
#define TILE_M  256
#define MAX_TILES (N_ATOMS_MAX / TILE_M + NTYPE)  // 516
#define BLOCK   512

// ---------------- smem layout (byte offsets) ----------------
// A: [blk16 0..15][grp 0..15][lane 0..31] x 16 B   (fragment-order, lane^(grp&7) swizzle)
// B: per-group rings: [gn 0..3][slot 0..3][bb 0..1][p 0..3][lane 0..31] x 16 B (4 KB/stage)
#define B_OFF_F    0                    // s_F[256] floats
#define B_OFF_IDX  1024                 // s_idx[256] ints
#define B_OFF_B0   2048                 // s_b0[512] floats
#define B_OFF_W1   4096                 // s_w1[512] floats
#define B_OFF_A    6144                 // 128 KB
#define B_OFF_B    (B_OFF_A + 131072)   // 137216; 4 groups x 16 KB rings
#define SMEM_BYTES (B_OFF_B + 4 * 16384)   // 202752 B

// ---------------- device scratch ----------------
__device__ __half g_W0H[NTYPE * H1 * DQ];      // W0^T fp16, (chunk,group)-sliced fragment order
__device__ int    g_idx[NTYPE * N_ATOMS_MAX];  // per-type regions
__device__ int    g_cnt[NTYPE];
__device__ int    g_tileT[MAX_TILES];
__device__ int    g_tileLT[MAX_TILES];
__device__ int    g_ntiles;

// ---------------- helpers ----------------
static __device__ __forceinline__ uint32_t smem_u32(const void* p) {
    uint32_t a;
    asm("{ .reg .u64 t; cvta.to.shared.u64 t, %1; cvt.u32.u64 %0, t; }" : "=r"(a) : "l"(p));
    return a;
}
static __device__ __forceinline__ void cp16(uint32_t dst, const void* src) {
    asm volatile("cp.async.cg.shared.global [%0], [%1], 16;" :: "r"(dst), "l"(src));
}
static __device__ __forceinline__ float tanh_fast(float x) {
    float y;
    asm("tanh.approx.f32 %0, %1;" : "=f"(y) : "f"(x));
    return y;
}
static __device__ __forceinline__ uint32_t pack_h2(float lo, float hi) {
    uint32_t r;
    asm("cvt.rn.f16x2.f32 %0, %1, %2;" : "=r"(r) : "f"(hi), "f"(lo));
    return r;
}
static __device__ __forceinline__ void mma_f16(float* c, uint32_t a0, uint32_t a1,
                                               uint32_t a2, uint32_t a3,
                                               uint32_t b0, uint32_t b1) {
    asm volatile(
        "mma.sync.aligned.m16n8k16.row.col.f32.f16.f16.f32 "
        "{%0,%1,%2,%3}, {%4,%5,%6,%7}, {%8,%9}, {%0,%1,%2,%3};"
        : "+f"(c[0]), "+f"(c[1]), "+f"(c[2]), "+f"(c[3])
        : "r"(a0), "r"(a1), "r"(a2), "r"(a3), "r"(b0), "r"(b1));
}
static __device__ __forceinline__ void group_bar(int id) {
    asm volatile("bar.sync %0, 128;" :: "r"(id) : "memory");
}

// ---------------- prep 1: init counters + W0 transpose into sliced fragment-order ----
// grid 512 x 256 thr. Blocks map (kx 0..7, jy 0..15, t 0..3).
__global__ void k_init_transpose(const float* __restrict__ W0) {
    if (blockIdx.x == 0 && threadIdx.x < NTYPE) g_cnt[threadIdx.x] = 0;
    __shared__ float tile[32][33];
    const int bid = blockIdx.x;
    const int kx = bid & 7, jy = (bid >> 3) & 15, t = bid >> 7;
    const int k0 = kx * 32, j0 = jy * 32;
    const int x = threadIdx.x & 31, y0 = threadIdx.x >> 5;   // 32 x 8
#pragma unroll
    for (int dy = 0; dy < 32; dy += 8) {
        int k = k0 + y0 + dy, j = j0 + x;
        tile[y0 + dy][x] = W0[((size_t)t * DQ + k) * H1 + j];
    }
    __syncthreads();
#pragma unroll
    for (int dy = 0; dy < 32; dy += 8) {
        const int j = j0 + y0 + dy;      // H1 index (n)
        const int k = k0 + x;            // DQ index
        const int ng   = j >> 7;         // 128-col n-group
        const int blkn = (j >> 4) & 7;   // 16-col block within group
        const int gn   = blkn >> 1;      // warpN group that reads this block
        const int bb   = blkn & 1;
        const int rb   = j & 15;
        const int jj = rb >> 3, g = rb & 7;
        const int kc = k >> 6;           // 64-k chunk
        const int p  = (k >> 4) & 3;     // k16 step within chunk
        const int ki = k & 15;
        const int tg = (ki >> 1) & 3;
        const int posq = ((ki >> 3) << 1) | (ki & 1);
        const int lane = (g * 4 + tg) ^ p;   // bake read swizzle
        const int ci = ng * 4 + kc;
        // (ci, gn) slice of 2048 halfs (4 KB) is contiguous
        const int halfIdx = (((((ci * 4 + gn) * 2 + bb) * 4 + p) * 32 + lane) << 3) + jj * 4 + posq;
        g_W0H[(size_t)t * (H1 * DQ) + halfIdx] = __float2half_rn(tile[x][y0 + dy]);
    }
}

// ---------------- prep 2: scatter with block-aggregated atomics ----------------
__global__ void k_scatter(const int* __restrict__ Z, int n) {
    __shared__ int wcnt[8][NTYPE];
    __shared__ int wbase[8][NTYPE];
    __shared__ int blkbase[NTYPE];
    const int i = blockIdx.x * blockDim.x + threadIdx.x;
    const int lane = threadIdx.x & 31, w = threadIdx.x >> 5;
    int z = -1, rank = 0;
    if (i < n) {
        z = Z[i];
#pragma unroll
        for (int t = 0; t < NTYPE; t++) {
            unsigned m = __ballot_sync(0xffffffffu, z == t);
            if (lane == 0) wcnt[w][t] = __popc(m);
            if (z == t) rank = __popc(m & ((1u << lane) - 1u));
        }
    } else if (lane == 0) {
#pragma unroll
        for (int t = 0; t < NTYPE; t++) wcnt[w][t] = 0;
    }
    __syncthreads();
    if (threadIdx.x < NTYPE) {
        const int t = threadIdx.x;
        int s = 0;
#pragma unroll
        for (int w2 = 0; w2 < 8; w2++) { wbase[w2][t] = s; s += wcnt[w2][t]; }
        blkbase[t] = atomicAdd(&g_cnt[t], s);
    }
    __syncthreads();
    if (z >= 0) g_idx[z * N_ATOMS_MAX + blkbase[z] + wbase[w][z] + rank] = i;
}

// ---------------- prep 3: tile table ----------------
__global__ void k_tiles() {
    __shared__ int ts[NTYPE + 1];
    if (threadIdx.x == 0) {
        int ti = 0;
        for (int t = 0; t < NTYPE; t++) {
            ts[t] = ti;
            ti += (g_cnt[t] + TILE_M - 1) / TILE_M;
        }
        ts[NTYPE] = ti;
        g_ntiles = ti;
    }
    __syncthreads();
    const int nt = ts[NTYPE];
    for (int ti = threadIdx.x; ti < nt; ti += blockDim.x) {
        int t = 0;
        while (t < NTYPE - 1 && ti >= ts[t + 1]) t++;
        g_tileT[ti] = t;
        g_tileLT[ti] = ti - ts[t];
    }
}

// ---------------- main fused GEMM + tanh + dot kernel ----------------
// Per-group stage load: 4 KB, 128 group threads x 2 cp16
static __device__ __forceinline__ void load_B_stage(int ci, int gn, uint32_t sB_u32,
                                                    const __half* __restrict__ w0h, int gtid) {
    const uint32_t dst0 = sB_u32 + gn * 16384 + (ci & 3) * 4096;
    const __half* src0 = w0h + (ci * 4 + gn) * 2048;
    cp16(dst0 + gtid * 16, src0 + gtid * 8);
    cp16(dst0 + (128 + gtid) * 16, src0 + (128 + gtid) * 8);
    asm volatile("cp.async.commit_group;" ::: "memory");
}

__global__ void __launch_bounds__(BLOCK, 1)
k_gemm(const float* __restrict__ q, const float* __restrict__ b0,
       const float* __restrict__ W1, const float* __restrict__ b1v,
       float* __restrict__ out) {
    extern __shared__ char smem[];
    const int tid = threadIdx.x;
    const int wid = tid >> 5, lane = tid & 31;
    const int g = lane >> 2, tig = lane & 3;
    const int warpM = wid & 3, warpN = wid >> 2;   // contiguous 4-warp N-groups
    const int gtid = tid & 127;                    // thread id within group
    const int bid = blockIdx.x;

    if (bid >= g_ntiles) return;

    const int t = g_tileT[bid], lt = g_tileLT[bid];
    const int cnt = g_cnt[t];
    const int row0 = lt * TILE_M;

    float*  s_F   = (float*)(smem + B_OFF_F);
    int*    s_idx = (int*)(smem + B_OFF_IDX);
    float*  s_b0  = (float*)(smem + B_OFF_B0);
    float*  s_w1  = (float*)(smem + B_OFF_W1);
    char*   s_A   = smem + B_OFF_A;
    char*   s_B   = smem + B_OFF_B;

    if (tid < TILE_M) {
        int r = row0 + tid;
        s_idx[tid] = g_idx[t * N_ATOMS_MAX + (r < cnt ? r : row0)];
        s_F[tid] = 0.0f;
    }
    s_b0[tid] = b0[t * H1 + tid];
    s_w1[tid] = W1[t * H1 + tid];
    __syncthreads();   // s_idx visible

    const __half* w0h = g_W0H + (size_t)t * (H1 * DQ);
    const uint32_t sB_u32 = smem_u32(s_B);

    // per-group prologue: stages 0,1,2 in flight
    load_B_stage(0, warpN, sB_u32, w0h, gtid);
    load_B_stage(1, warpN, sB_u32, w0h, gtid);
    load_B_stage(2, warpN, sB_u32, w0h, gtid);

    // A gather: 256 rows x 16 k16-groups; fragment-order store with lane^(grp&7) swizzle
#pragma unroll
    for (int o = 0; o < 8; o++) {
        const int lin = o * BLOCK + tid;        // 4096 tasks
        const int grp = lin & 15, row = lin >> 4;
        const float* src = q + (size_t)s_idx[row] * DQ + grp * 16;
        float v[16];
#pragma unroll
        for (int s = 0; s < 4; s++) {
            const float4 f4 = *(const float4*)(src + s * 4);
            v[s * 4 + 0] = f4.x; v[s * 4 + 1] = f4.y;
            v[s * 4 + 2] = f4.z; v[s * 4 + 3] = f4.w;
        }
        const int blk = row >> 4, half = (row >> 3) & 1, gg = row & 7;
        char* dbase = s_A + ((blk * 16 + grp) << 9) + half * 8;
        const int sw = grp & 7;
#pragma unroll
        for (int tt = 0; tt < 4; tt++) {
            uint2 pr;
            pr.x = pack_h2(v[tt * 2],     v[tt * 2 + 1]);
            pr.y = pack_h2(v[tt * 2 + 8], v[tt * 2 + 9]);
            *(uint2*)(dbase + (((gg * 4 + tt) ^ sw) << 4)) = pr;
        }
    }
    __syncthreads();   // A tile visible to all warps

    const float b1s = b1v[0];
    const int barId = warpN + 1;

#pragma unroll 1
    for (int ng = 0; ng < 4; ng++) {            // 128-col n-groups
        float acc[4][4][4];                     // [i: 16-row blk][f = bb*2+jj][c]
#pragma unroll
        for (int i = 0; i < 4; i++)
#pragma unroll
            for (int f = 0; f < 4; f++)
#pragma unroll
                for (int c = 0; c < 4; c++) acc[i][f][c] = 0.0f;

#pragma unroll 1
        for (int kc = 0; kc < 4; kc++) {
            const int ci = ng * 4 + kc;
            if (ci < 14)       asm volatile("cp.async.wait_group 2;" ::: "memory");
            else if (ci == 14) asm volatile("cp.async.wait_group 1;" ::: "memory");
            else               asm volatile("cp.async.wait_group 0;" ::: "memory");
            group_bar(barId);   // group's stage ci visible; group done reading stage ci-1

            if (ci + 3 < 16) load_B_stage(ci + 3, warpN, sB_u32, w0h, gtid);

            const char* As = s_A + (warpM * 4 * 16 + kc * 4) * 512;         // + (i*16+p)*512
            const char* Bs = s_B + warpN * 16384 + (ci & 3) * 4096;         // + (bb*4+p)*512
#pragma unroll
            for (int p = 0; p < 4; p++) {
                const int swA = (lane ^ (((kc & 1) << 2) | p)) << 4;
                const int swB = (lane ^ p) << 4;
                uint4 A[4];
#pragma unroll
                for (int i = 0; i < 4; i++)
                    A[i] = *(const uint4*)(As + (i * 16 + p) * 512 + swA);
                const uint4 B0 = *(const uint4*)(Bs + p * 512 + swB);
                const uint4 B1 = *(const uint4*)(Bs + (4 + p) * 512 + swB);
                // A uint4: {a0, a2, a1, a3}; B uint4: {b0_j0, b1_j0, b0_j1, b1_j1}
#pragma unroll
                for (int i = 0; i < 4; i++) {
                    mma_f16(acc[i][0], A[i].x, A[i].z, A[i].y, A[i].w, B0.x, B0.y);
                    mma_f16(acc[i][1], A[i].x, A[i].z, A[i].y, A[i].w, B0.z, B0.w);
                    mma_f16(acc[i][2], A[i].x, A[i].z, A[i].y, A[i].w, B1.x, B1.y);
                    mma_f16(acc[i][3], A[i].x, A[i].z, A[i].y, A[i].w, B1.z, B1.w);
                }
            }
        }

        // ---- epilogue: tanh(h + b0) * W1, reduce over this 128-col group ----
        float fa[4][2];
#pragma unroll
        for (int i = 0; i < 4; i++) { fa[i][0] = 0.0f; fa[i][1] = 0.0f; }
#pragma unroll
        for (int i = 0; i < 4; i++)
#pragma unroll
            for (int f = 0; f < 4; f++) {
                const int bb = f >> 1, jj = f & 1;
#pragma unroll
                for (int c = 0; c < 4; c++) {
                    const int colg = ng * 128 + warpN * 32 + bb * 16 + jj * 8 + tig * 2 + (c & 1);
                    const float h = tanh_fast(acc[i][f][c] + s_b0[colg]);
                    fa[i][c >> 1] = fmaf(h, s_w1[colg], fa[i][c >> 1]);
                }
            }
#pragma unroll
        for (int i = 0; i < 4; i++)
#pragma unroll
            for (int hh = 0; hh < 2; hh++) {
                fa[i][hh] += __shfl_xor_sync(0xffffffffu, fa[i][hh], 1);
                fa[i][hh] += __shfl_xor_sync(0xffffffffu, fa[i][hh], 2);
            }
        if (tig == 0) {
#pragma unroll
            for (int i = 0; i < 4; i++)
#pragma unroll
                for (int hh = 0; hh < 2; hh++) {
                    const int m = warpM * 64 + i * 16 + hh * 8 + g;
                    atomicAdd(&s_F[m], fa[i][hh]);
                }
        }
    }

    __syncthreads();   // all groups' s_F contributions done
    if (tid < TILE_M) {
        if (row0 + tid < cnt) out[s_idx[tid]] = s_F[tid] + b1s;
    }
}

// ---------------- launch ----------------
extern "C" void kernel_launch(void* const* d_in, const int* in_sizes, int n_in,
                              void* d_out, int out_size) {
    const float* q  = (const float*)d_in[0];
    const int*   Z  = (const int*)d_in[1];
    const float* W0 = (const float*)d_in[2];
    const float* b0 = (const float*)d_in[3];
    const float* W1 = (const float*)d_in[4];
    const float* b1 = (const float*)d_in[5];
    float* out = (float*)d_out;
    int n = in_sizes[1];

    k_init_transpose<<<512, 256>>>(W0);
    k_scatter<<<(n + 255) / 256, 256>>>(Z, n);
    k_tiles<<<1, 256>>>();

    cudaFuncSetAttribute(k_gemm, cudaFuncAttributeMaxDynamicSharedMemorySize, SMEM_BYTES);
    k_gemm<<<MAX_TILES, BLOCK, SMEM_BYTES>>>(q, b0, W1, b1, out);
}

// round 11
// speedup vs baseline: 2.9754x; 1.2087x over previous
#include <cuda_runtime.h>
#include <cuda_fp16.h>
#include <cstdint>

// ---------------- problem constants ----------------
#define N_ATOMS_MAX 131072
#define DQ      256
#define H1      512
#define NTYPE   4
#define TILE_M  128
#define MAX_TILES (N_ATOMS_MAX / TILE_M + NTYPE)  // 1028
#define BLOCK   256

// ---------------- smem layout (byte offsets) ----------------
// A: [blk16 0..7][grp 0..15][lane 0..31] x 16 B   (fragment-order, lane^(grp&7) swizzle)
// B: per-group rings: [gn 0..3][slot 0..1][bb 0..1][p 0..3][lane 0..31] x 16 B (4 KB/stage)
#define B_OFF_F    0                    // s_F[128] floats
#define B_OFF_IDX  512                  // s_idx[128] ints
#define B_OFF_B0   1024                 // s_b0[512] floats
#define B_OFF_W1   3072                 // s_w1[512] floats
#define B_OFF_A    5120                 // 64 KB
#define B_OFF_B    (B_OFF_A + 65536)    // 70656; 4 groups x 8 KB rings
#define SMEM_BYTES (B_OFF_B + 4 * 8192)    // 103424 B -> 2 CTAs / SM

// ---------------- device scratch ----------------
__device__ __half g_W0H[NTYPE * H1 * DQ];      // W0^T fp16, (chunk,group)-sliced fragment order
__device__ int    g_idx[NTYPE * N_ATOMS_MAX];  // per-type regions
__device__ int    g_cnt[NTYPE];
__device__ int    g_tileT[MAX_TILES];
__device__ int    g_tileLT[MAX_TILES];
__device__ int    g_ntiles;

// ---------------- helpers ----------------
static __device__ __forceinline__ uint32_t smem_u32(const void* p) {
    uint32_t a;
    asm("{ .reg .u64 t; cvta.to.shared.u64 t, %1; cvt.u32.u64 %0, t; }" : "=r"(a) : "l"(p));
    return a;
}
static __device__ __forceinline__ void cp16(uint32_t dst, const void* src) {
    asm volatile("cp.async.cg.shared.global [%0], [%1], 16;" :: "r"(dst), "l"(src));
}
static __device__ __forceinline__ float tanh_fast(float x) {
    float y;
    asm("tanh.approx.f32 %0, %1;" : "=f"(y) : "f"(x));
    return y;
}
static __device__ __forceinline__ uint32_t pack_h2(float lo, float hi) {
    uint32_t r;
    asm("cvt.rn.f16x2.f32 %0, %1, %2;" : "=r"(r) : "f"(hi), "f"(lo));
    return r;
}
static __device__ __forceinline__ void mma_f16(float* c, uint32_t a0, uint32_t a1,
                                               uint32_t a2, uint32_t a3,
                                               uint32_t b0, uint32_t b1) {
    asm volatile(
        "mma.sync.aligned.m16n8k16.row.col.f32.f16.f16.f32 "
        "{%0,%1,%2,%3}, {%4,%5,%6,%7}, {%8,%9}, {%0,%1,%2,%3};"
        : "+f"(c[0]), "+f"(c[1]), "+f"(c[2]), "+f"(c[3])
        : "r"(a0), "r"(a1), "r"(a2), "r"(a3), "r"(b0), "r"(b1));
}
static __device__ __forceinline__ void group_bar(int id) {
    asm volatile("bar.sync %0, 64;" :: "r"(id) : "memory");
}

// ---------------- prep 1: init counters + W0 transpose into sliced fragment-order ----
// grid 512 x 256 thr. Blocks map (kx 0..7, jy 0..15, t 0..3).
__global__ void k_init_transpose(const float* __restrict__ W0) {
    if (blockIdx.x == 0 && threadIdx.x < NTYPE) g_cnt[threadIdx.x] = 0;
    __shared__ float tile[32][33];
    const int bid = blockIdx.x;
    const int kx = bid & 7, jy = (bid >> 3) & 15, t = bid >> 7;
    const int k0 = kx * 32, j0 = jy * 32;
    const int x = threadIdx.x & 31, y0 = threadIdx.x >> 5;   // 32 x 8
#pragma unroll
    for (int dy = 0; dy < 32; dy += 8) {
        int k = k0 + y0 + dy, j = j0 + x;
        tile[y0 + dy][x] = W0[((size_t)t * DQ + k) * H1 + j];
    }
    __syncthreads();
#pragma unroll
    for (int dy = 0; dy < 32; dy += 8) {
        const int j = j0 + y0 + dy;      // H1 index (n)
        const int k = k0 + x;            // DQ index
        const int ng   = j >> 7;         // 128-col n-group
        const int blkn = (j >> 4) & 7;   // 16-col block within group
        const int gn   = blkn >> 1;      // warpN group that reads this block
        const int bb   = blkn & 1;
        const int rb   = j & 15;
        const int jj = rb >> 3, g = rb & 7;
        const int kc = k >> 6;           // 64-k chunk
        const int p  = (k >> 4) & 3;     // k16 step within chunk
        const int ki = k & 15;
        const int tg = (ki >> 1) & 3;
        const int posq = ((ki >> 3) << 1) | (ki & 1);
        const int lane = (g * 4 + tg) ^ p;   // bake read swizzle
        const int ci = ng * 4 + kc;
        // (ci, gn) slice of 2048 halfs (4 KB) is contiguous
        const int halfIdx = (((((ci * 4 + gn) * 2 + bb) * 4 + p) * 32 + lane) << 3) + jj * 4 + posq;
        g_W0H[(size_t)t * (H1 * DQ) + halfIdx] = __float2half_rn(tile[x][y0 + dy]);
    }
}

// ---------------- prep 2: scatter with block-aggregated atomics ----------------
__global__ void k_scatter(const int* __restrict__ Z, int n) {
    __shared__ int wcnt[8][NTYPE];
    __shared__ int wbase[8][NTYPE];
    __shared__ int blkbase[NTYPE];
    const int i = blockIdx.x * blockDim.x + threadIdx.x;
    const int lane = threadIdx.x & 31, w = threadIdx.x >> 5;
    int z = -1, rank = 0;
    if (i < n) {
        z = Z[i];
#pragma unroll
        for (int t = 0; t < NTYPE; t++) {
            unsigned m = __ballot_sync(0xffffffffu, z == t);
            if (lane == 0) wcnt[w][t] = __popc(m);
            if (z == t) rank = __popc(m & ((1u << lane) - 1u));
        }
    } else if (lane == 0) {
#pragma unroll
        for (int t = 0; t < NTYPE; t++) wcnt[w][t] = 0;
    }
    __syncthreads();
    if (threadIdx.x < NTYPE) {
        const int t = threadIdx.x;
        int s = 0;
#pragma unroll
        for (int w2 = 0; w2 < 8; w2++) { wbase[w2][t] = s; s += wcnt[w2][t]; }
        blkbase[t] = atomicAdd(&g_cnt[t], s);
    }
    __syncthreads();
    if (z >= 0) g_idx[z * N_ATOMS_MAX + blkbase[z] + wbase[w][z] + rank] = i;
}

// ---------------- prep 3: tile table ----------------
__global__ void k_tiles() {
    __shared__ int ts[NTYPE + 1];
    if (threadIdx.x == 0) {
        int ti = 0;
        for (int t = 0; t < NTYPE; t++) {
            ts[t] = ti;
            ti += (g_cnt[t] + TILE_M - 1) / TILE_M;
        }
        ts[NTYPE] = ti;
        g_ntiles = ti;
    }
    __syncthreads();
    const int nt = ts[NTYPE];
    for (int ti = threadIdx.x; ti < nt; ti += blockDim.x) {
        int t = 0;
        while (t < NTYPE - 1 && ti >= ts[t + 1]) t++;
        g_tileT[ti] = t;
        g_tileLT[ti] = ti - ts[t];
    }
}

// ---------------- main fused GEMM + tanh + dot kernel ----------------
// Per-group 2-slot ring; stage = 4 KB, loaded by the group's 64 threads (4 cp16 each)
static __device__ __forceinline__ void load_B_stage(int ci, int gn, uint32_t sB_u32,
                                                    const __half* __restrict__ w0h, int gtid) {
    const uint32_t dst0 = sB_u32 + gn * 8192 + (ci & 1) * 4096;
    const __half* src0 = w0h + (ci * 4 + gn) * 2048;
#pragma unroll
    for (int o = 0; o < 4; o++) {
        const int lin = o * 64 + gtid;
        cp16(dst0 + lin * 16, src0 + lin * 8);
    }
    asm volatile("cp.async.commit_group;" ::: "memory");
}

__global__ void __launch_bounds__(BLOCK, 2)
k_gemm(const float* __restrict__ q, const float* __restrict__ b0,
       const float* __restrict__ W1, const float* __restrict__ b1v,
       float* __restrict__ out) {
    extern __shared__ char smem[];
    const int tid = threadIdx.x;
    const int wid = tid >> 5, lane = tid & 31;
    const int g = lane >> 2, tig = lane & 3;
    const int warpM = wid & 1, warpN = wid >> 1;   // 2M x 4N; warp tile 64 rows x 32 cols
    const int gtid = tid & 63;                     // thread id within 2-warp group
    const int bid = blockIdx.x;

    if (bid >= g_ntiles) return;

    const int t = g_tileT[bid], lt = g_tileLT[bid];
    const int cnt = g_cnt[t];
    const int row0 = lt * TILE_M;

    float*  s_F   = (float*)(smem + B_OFF_F);
    int*    s_idx = (int*)(smem + B_OFF_IDX);
    float*  s_b0  = (float*)(smem + B_OFF_B0);
    float*  s_w1  = (float*)(smem + B_OFF_W1);
    char*   s_A   = smem + B_OFF_A;
    char*   s_B   = smem + B_OFF_B;

    const __half* w0h = g_W0H + (size_t)t * (H1 * DQ);
    const uint32_t sB_u32 = smem_u32(s_B);

    // prime group ring: stage 0 in flight (2-slot double buffer)
    load_B_stage(0, warpN, sB_u32, w0h, gtid);

    if (tid < TILE_M) {
        int r = row0 + tid;
        s_idx[tid] = g_idx[t * N_ATOMS_MAX + (r < cnt ? r : row0)];
        s_F[tid] = 0.0f;
    }
#pragma unroll
    for (int o = 0; o < 2; o++) {
        const int c = o * BLOCK + tid;
        s_b0[c] = b0[t * H1 + c];
        s_w1[c] = W1[t * H1 + c];
    }
    __syncthreads();   // s_idx visible

    // A gather: 128 rows x 16 k16-groups = 2048 tasks (8/thread)
#pragma unroll
    for (int o = 0; o < 8; o++) {
        const int lin = o * BLOCK + tid;
        const int grp = lin & 15, row = lin >> 4;
        const float* src = q + (size_t)s_idx[row] * DQ + grp * 16;
        float v[16];
#pragma unroll
        for (int s = 0; s < 4; s++) {
            const float4 f4 = *(const float4*)(src + s * 4);
            v[s * 4 + 0] = f4.x; v[s * 4 + 1] = f4.y;
            v[s * 4 + 2] = f4.z; v[s * 4 + 3] = f4.w;
        }
        const int blk = row >> 4, half = (row >> 3) & 1, gg = row & 7;
        char* dbase = s_A + ((blk * 16 + grp) << 9) + half * 8;
        const int sw = grp & 7;
#pragma unroll
        for (int tt = 0; tt < 4; tt++) {
            uint2 pr;
            pr.x = pack_h2(v[tt * 2],     v[tt * 2 + 1]);
            pr.y = pack_h2(v[tt * 2 + 8], v[tt * 2 + 9]);
            *(uint2*)(dbase + (((gg * 4 + tt) ^ sw) << 4)) = pr;
        }
    }
    __syncthreads();   // A tile visible to all warps

    const float b1s = b1v[0];
    const int barId = warpN + 1;

#pragma unroll 1
    for (int ng = 0; ng < 4; ng++) {            // 128-col n-groups
        float acc[4][4][4];                     // [i: 16-row blk][f = bb*2+jj][c]
#pragma unroll
        for (int i = 0; i < 4; i++)
#pragma unroll
            for (int f = 0; f < 4; f++)
#pragma unroll
                for (int c = 0; c < 4; c++) acc[i][f][c] = 0.0f;

#pragma unroll 1
        for (int kc = 0; kc < 4; kc++) {
            const int ci = ng * 4 + kc;
            asm volatile("cp.async.wait_group 0;" ::: "memory");   // stage ci arrived (this thread)
            group_bar(barId);   // all group threads arrived -> stage ci fully visible,
                                // and slot (ci+1)&1 is free (group done computing ci-1)
            if (ci + 1 < 16) load_B_stage(ci + 1, warpN, sB_u32, w0h, gtid);

            const char* As = s_A + (warpM * 4 * 16 + kc * 4) * 512;   // + (i*16+p)*512
            const char* Bs = s_B + warpN * 8192 + (ci & 1) * 4096;    // + (bb*4+p)*512
#pragma unroll
            for (int p = 0; p < 4; p++) {
                const int swA = (lane ^ (((kc & 1) << 2) | p)) << 4;
                const int swB = (lane ^ p) << 4;
                uint4 A[4];
#pragma unroll
                for (int i = 0; i < 4; i++)
                    A[i] = *(const uint4*)(As + (i * 16 + p) * 512 + swA);
                const uint4 B0 = *(const uint4*)(Bs + p * 512 + swB);
                const uint4 B1 = *(const uint4*)(Bs + (4 + p) * 512 + swB);
                // A uint4: {a0, a2, a1, a3}; B uint4: {b0_j0, b1_j0, b0_j1, b1_j1}
#pragma unroll
                for (int i = 0; i < 4; i++) {
                    mma_f16(acc[i][0], A[i].x, A[i].z, A[i].y, A[i].w, B0.x, B0.y);
                    mma_f16(acc[i][1], A[i].x, A[i].z, A[i].y, A[i].w, B0.z, B0.w);
                    mma_f16(acc[i][2], A[i].x, A[i].z, A[i].y, A[i].w, B1.x, B1.y);
                    mma_f16(acc[i][3], A[i].x, A[i].z, A[i].y, A[i].w, B1.z, B1.w);
                }
            }
        }

        // ---- epilogue: tanh(h + b0) * W1, reduce over this 128-col group ----
        float fa[4][2];
#pragma unroll
        for (int i = 0; i < 4; i++) { fa[i][0] = 0.0f; fa[i][1] = 0.0f; }
#pragma unroll
        for (int i = 0; i < 4; i++)
#pragma unroll
            for (int f = 0; f < 4; f++) {
                const int bb = f >> 1, jj = f & 1;
#pragma unroll
                for (int c = 0; c < 4; c++) {
                    const int colg = ng * 128 + warpN * 32 + bb * 16 + jj * 8 + tig * 2 + (c & 1);
                    const float h = tanh_fast(acc[i][f][c] + s_b0[colg]);
                    fa[i][c >> 1] = fmaf(h, s_w1[colg], fa[i][c >> 1]);
                }
            }
#pragma unroll
        for (int i = 0; i < 4; i++)
#pragma unroll
            for (int hh = 0; hh < 2; hh++) {
                fa[i][hh] += __shfl_xor_sync(0xffffffffu, fa[i][hh], 1);
                fa[i][hh] += __shfl_xor_sync(0xffffffffu, fa[i][hh], 2);
            }
        if (tig == 0) {
#pragma unroll
            for (int i = 0; i < 4; i++)
#pragma unroll
                for (int hh = 0; hh < 2; hh++) {
                    const int m = warpM * 64 + i * 16 + hh * 8 + g;
                    atomicAdd(&s_F[m], fa[i][hh]);
                }
        }
    }

    __syncthreads();   // all groups' s_F contributions done
    if (tid < TILE_M) {
        if (row0 + tid < cnt) out[s_idx[tid]] = s_F[tid] + b1s;
    }
}

// ---------------- launch ----------------
extern "C" void kernel_launch(void* const* d_in, const int* in_sizes, int n_in,
                              void* d_out, int out_size) {
    const float* q  = (const float*)d_in[0];
    const int*   Z  = (const int*)d_in[1];
    const float* W0 = (const float*)d_in[2];
    const float* b0 = (const float*)d_in[3];
    const float* W1 = (const float*)d_in[4];
    const float* b1 = (const float*)d_in[5];
    float* out = (float*)d_out;
    int n = in_sizes[1];

    k_init_transpose<<<512, 256>>>(W0);
    k_scatter<<<(n + 255) / 256, 256>>>(Z, n);
    k_tiles<<<1, 256>>>();

    cudaFuncSetAttribute(k_gemm, cudaFuncAttributeMaxDynamicSharedMemorySize, SMEM_BYTES);
    k_gemm<<<MAX_TILES, BLOCK, SMEM_BYTES>>>(q, b0, W1, b1, out);
}

// round 12
// speedup vs baseline: 3.0225x; 1.0158x over previous
#include <cuda_runtime.h>
#include <cuda_fp16.h>
#include <cstdint>

// ---------------- problem constants ----------------
#define N_ATOMS_MAX 131072
#define DQ      256
#define H1      512
#define NTYPE   4
#define TILE_M  128
#define MAX_TILES (N_ATOMS_MAX / TILE_M + NTYPE)  // 1028
#define BLOCK   256

// ---------------- smem layout (byte offsets) ----------------
// A: [blk16 0..7][grp 0..15][lane 0..31] x 16 B   (fragment-order, lane^(grp&7) swizzle)
// B: per-group rings: [gn 0..3][slot 0..1][bb 0..1][p 0..3][lane 0..31] x 16 B (4 KB/stage)
#define B_OFF_F    0                    // s_F[128] floats
#define B_OFF_IDX  512                  // s_idx[128] ints
#define B_OFF_B0   1024                 // s_b0[512] floats
#define B_OFF_W1   3072                 // s_w1[512] floats
#define B_OFF_A    5120                 // 64 KB
#define B_OFF_B    (B_OFF_A + 65536)    // 70656; 4 groups x 8 KB rings
#define SMEM_BYTES (B_OFF_B + 4 * 8192)    // 103424 B -> 2 CTAs / SM

// ---------------- device scratch ----------------
__device__ __half g_W0H[NTYPE * H1 * DQ];      // W0^T fp16, (chunk,group)-sliced fragment order
__device__ int    g_idx[NTYPE * N_ATOMS_MAX];  // per-type regions
__device__ int    g_cnt[NTYPE];

// ---------------- helpers ----------------
static __device__ __forceinline__ uint32_t smem_u32(const void* p) {
    uint32_t a;
    asm("{ .reg .u64 t; cvta.to.shared.u64 t, %1; cvt.u32.u64 %0, t; }" : "=r"(a) : "l"(p));
    return a;
}
static __device__ __forceinline__ void cp16(uint32_t dst, const void* src) {
    asm volatile("cp.async.cg.shared.global [%0], [%1], 16;" :: "r"(dst), "l"(src));
}
static __device__ __forceinline__ float tanh_fast(float x) {
    float y;
    asm("tanh.approx.f32 %0, %1;" : "=f"(y) : "f"(x));
    return y;
}
static __device__ __forceinline__ uint32_t pack_h2(float lo, float hi) {
    uint32_t r;
    asm("cvt.rn.f16x2.f32 %0, %1, %2;" : "=r"(r) : "f"(hi), "f"(lo));
    return r;
}
static __device__ __forceinline__ void mma_f16(float* c, uint32_t a0, uint32_t a1,
                                               uint32_t a2, uint32_t a3,
                                               uint32_t b0, uint32_t b1) {
    asm volatile(
        "mma.sync.aligned.m16n8k16.row.col.f32.f16.f16.f32 "
        "{%0,%1,%2,%3}, {%4,%5,%6,%7}, {%8,%9}, {%0,%1,%2,%3};"
        : "+f"(c[0]), "+f"(c[1]), "+f"(c[2]), "+f"(c[3])
        : "r"(a0), "r"(a1), "r"(a2), "r"(a3), "r"(b0), "r"(b1));
}
static __device__ __forceinline__ void group_bar(int id) {
    asm volatile("bar.sync %0, 64;" :: "r"(id) : "memory");
}

// ---------------- prep 1: init counters + W0 transpose into sliced fragment-order ----
// grid 512 x 256 thr. Blocks map (kx 0..7, jy 0..15, t 0..3).
__global__ void k_init_transpose(const float* __restrict__ W0) {
    if (blockIdx.x == 0 && threadIdx.x < NTYPE) g_cnt[threadIdx.x] = 0;
    __shared__ float tile[32][33];
    const int bid = blockIdx.x;
    const int kx = bid & 7, jy = (bid >> 3) & 15, t = bid >> 7;
    const int k0 = kx * 32, j0 = jy * 32;
    const int x = threadIdx.x & 31, y0 = threadIdx.x >> 5;   // 32 x 8
#pragma unroll
    for (int dy = 0; dy < 32; dy += 8) {
        int k = k0 + y0 + dy, j = j0 + x;
        tile[y0 + dy][x] = W0[((size_t)t * DQ + k) * H1 + j];
    }
    __syncthreads();
#pragma unroll
    for (int dy = 0; dy < 32; dy += 8) {
        const int j = j0 + y0 + dy;      // H1 index (n)
        const int k = k0 + x;            // DQ index
        const int ng   = j >> 7;         // 128-col n-group
        const int blkn = (j >> 4) & 7;   // 16-col block within group
        const int gn   = blkn >> 1;      // warpN group that reads this block
        const int bb   = blkn & 1;
        const int rb   = j & 15;
        const int jj = rb >> 3, g = rb & 7;
        const int kc = k >> 6;           // 64-k chunk
        const int p  = (k >> 4) & 3;     // k16 step within chunk
        const int ki = k & 15;
        const int tg = (ki >> 1) & 3;
        const int posq = ((ki >> 3) << 1) | (ki & 1);
        const int lane = (g * 4 + tg) ^ p;   // bake read swizzle
        const int ci = ng * 4 + kc;
        // (ci, gn) slice of 2048 halfs (4 KB) is contiguous
        const int halfIdx = (((((ci * 4 + gn) * 2 + bb) * 4 + p) * 32 + lane) << 3) + jj * 4 + posq;
        g_W0H[(size_t)t * (H1 * DQ) + halfIdx] = __float2half_rn(tile[x][y0 + dy]);
    }
}

// ---------------- prep 2: scatter with block-aggregated atomics ----------------
__global__ void k_scatter(const int* __restrict__ Z, int n) {
    __shared__ int wcnt[8][NTYPE];
    __shared__ int wbase[8][NTYPE];
    __shared__ int blkbase[NTYPE];
    const int i = blockIdx.x * blockDim.x + threadIdx.x;
    const int lane = threadIdx.x & 31, w = threadIdx.x >> 5;
    int z = -1, rank = 0;
    if (i < n) {
        z = Z[i];
#pragma unroll
        for (int t = 0; t < NTYPE; t++) {
            unsigned m = __ballot_sync(0xffffffffu, z == t);
            if (lane == 0) wcnt[w][t] = __popc(m);
            if (z == t) rank = __popc(m & ((1u << lane) - 1u));
        }
    } else if (lane == 0) {
#pragma unroll
        for (int t = 0; t < NTYPE; t++) wcnt[w][t] = 0;
    }
    __syncthreads();
    if (threadIdx.x < NTYPE) {
        const int t = threadIdx.x;
        int s = 0;
#pragma unroll
        for (int w2 = 0; w2 < 8; w2++) { wbase[w2][t] = s; s += wcnt[w2][t]; }
        blkbase[t] = atomicAdd(&g_cnt[t], s);
    }
    __syncthreads();
    if (z >= 0) g_idx[z * N_ATOMS_MAX + blkbase[z] + wbase[w][z] + rank] = i;
}

// ---------------- main fused GEMM + tanh + dot kernel ----------------
// Per-group 2-slot ring; stage = 4 KB, loaded by the group's 64 threads (4 cp16 each)
static __device__ __forceinline__ void load_B_stage(int ci, int gn, uint32_t sB_u32,
                                                    const __half* __restrict__ w0h, int gtid) {
    const uint32_t dst0 = sB_u32 + gn * 8192 + (ci & 1) * 4096;
    const __half* src0 = w0h + (ci * 4 + gn) * 2048;
#pragma unroll
    for (int o = 0; o < 4; o++) {
        const int lin = o * 64 + gtid;
        cp16(dst0 + lin * 16, src0 + lin * 8);
    }
    asm volatile("cp.async.commit_group;" ::: "memory");
}

__global__ void __launch_bounds__(BLOCK, 2)
k_gemm(const float* __restrict__ q, const float* __restrict__ b0,
       const float* __restrict__ W1, const float* __restrict__ b1v,
       float* __restrict__ out) {
    extern __shared__ char smem[];
    const int tid = threadIdx.x;
    const int wid = tid >> 5, lane = tid & 31;
    const int g = lane >> 2, tig = lane & 3;
    const int warpM = wid & 1, warpN = wid >> 1;   // 2M x 4N; warp tile 64 rows x 32 cols
    const int gtid = tid & 63;                     // thread id within 2-warp group

    // ---- tile table, computed in-kernel from g_cnt (folds old k_tiles) ----
    const int c0 = g_cnt[0], c1 = g_cnt[1], c2 = g_cnt[2], c3 = g_cnt[3];
    const int n0 = (c0 + TILE_M - 1) >> 7;
    const int n1 = (c1 + TILE_M - 1) >> 7;
    const int n2 = (c2 + TILE_M - 1) >> 7;
    const int n3 = (c3 + TILE_M - 1) >> 7;
    const int bid = blockIdx.x;
    int t, lt, cnt;
    if (bid < n0)                { t = 0; lt = bid;                cnt = c0; }
    else if (bid < n0 + n1)      { t = 1; lt = bid - n0;           cnt = c1; }
    else if (bid < n0 + n1 + n2) { t = 2; lt = bid - n0 - n1;      cnt = c2; }
    else if (bid < n0 + n1 + n2 + n3) { t = 3; lt = bid - n0 - n1 - n2; cnt = c3; }
    else return;
    const int row0 = lt * TILE_M;

    float*  s_F   = (float*)(smem + B_OFF_F);
    int*    s_idx = (int*)(smem + B_OFF_IDX);
    float*  s_b0  = (float*)(smem + B_OFF_B0);
    float*  s_w1  = (float*)(smem + B_OFF_W1);
    char*   s_A   = smem + B_OFF_A;
    char*   s_B   = smem + B_OFF_B;

    const __half* w0h = g_W0H + (size_t)t * (H1 * DQ);
    const uint32_t sB_u32 = smem_u32(s_B);

    // prime group ring: stage 0 in flight (2-slot double buffer)
    load_B_stage(0, warpN, sB_u32, w0h, gtid);

    if (tid < TILE_M) {
        int r = row0 + tid;
        s_idx[tid] = g_idx[t * N_ATOMS_MAX + (r < cnt ? r : row0)];
        s_F[tid] = 0.0f;
    }
#pragma unroll
    for (int o = 0; o < 2; o++) {
        const int c = o * BLOCK + tid;
        s_b0[c] = b0[t * H1 + c];
        s_w1[c] = W1[t * H1 + c];
    }
    __syncthreads();   // s_idx visible

    // A gather: 128 rows x 16 k16-groups = 2048 tasks (8/thread)
#pragma unroll
    for (int o = 0; o < 8; o++) {
        const int lin = o * BLOCK + tid;
        const int grp = lin & 15, row = lin >> 4;
        const float* src = q + (size_t)s_idx[row] * DQ + grp * 16;
        float v[16];
#pragma unroll
        for (int s = 0; s < 4; s++) {
            const float4 f4 = *(const float4*)(src + s * 4);
            v[s * 4 + 0] = f4.x; v[s * 4 + 1] = f4.y;
            v[s * 4 + 2] = f4.z; v[s * 4 + 3] = f4.w;
        }
        const int blk = row >> 4, half = (row >> 3) & 1, gg = row & 7;
        char* dbase = s_A + ((blk * 16 + grp) << 9) + half * 8;
        const int sw = grp & 7;
#pragma unroll
        for (int tt = 0; tt < 4; tt++) {
            uint2 pr;
            pr.x = pack_h2(v[tt * 2],     v[tt * 2 + 1]);
            pr.y = pack_h2(v[tt * 2 + 8], v[tt * 2 + 9]);
            *(uint2*)(dbase + (((gg * 4 + tt) ^ sw) << 4)) = pr;
        }
    }
    __syncthreads();   // A tile visible to all warps

    const float b1s = b1v[0];
    const int barId = warpN + 1;

#pragma unroll 1
    for (int ng = 0; ng < 4; ng++) {            // 128-col n-groups
        float acc[4][4][4];                     // [i: 16-row blk][f = bb*2+jj][c]
#pragma unroll
        for (int i = 0; i < 4; i++)
#pragma unroll
            for (int f = 0; f < 4; f++)
#pragma unroll
                for (int c = 0; c < 4; c++) acc[i][f][c] = 0.0f;

#pragma unroll 1
        for (int kc = 0; kc < 4; kc++) {
            const int ci = ng * 4 + kc;
            asm volatile("cp.async.wait_group 0;" ::: "memory");   // stage ci arrived (this thread)
            group_bar(barId);   // all group threads arrived -> stage ci fully visible,
                                // and slot (ci+1)&1 is free (group done computing ci-1)
            if (ci + 1 < 16) load_B_stage(ci + 1, warpN, sB_u32, w0h, gtid);

            const char* As = s_A + (warpM * 64 + kc * 4) * 512;   // + (i*16+p)*512
            const char* Bs = s_B + warpN * 8192 + (ci & 1) * 4096;    // + (bb*4+p)*512
            const int kbase = (kc & 1) << 2;

            // software-pipelined fragments: double-buffer A/B regs across p
            uint4 Ab[2][4], Bb[2][2];
            {
                const int swA = (lane ^ kbase) << 4;
                const int swB = lane << 4;
#pragma unroll
                for (int i = 0; i < 4; i++)
                    Ab[0][i] = *(const uint4*)(As + (i * 16) * 512 + swA);
                Bb[0][0] = *(const uint4*)(Bs + swB);
                Bb[0][1] = *(const uint4*)(Bs + 4 * 512 + swB);
            }
#pragma unroll
            for (int p = 0; p < 4; p++) {
                const int cur = p & 1, nxt = cur ^ 1;
                if (p < 3) {
                    const int pn = p + 1;
                    const int swA = (lane ^ (kbase | pn)) << 4;
                    const int swB = (lane ^ pn) << 4;
#pragma unroll
                    for (int i = 0; i < 4; i++)
                        Ab[nxt][i] = *(const uint4*)(As + (i * 16 + pn) * 512 + swA);
                    Bb[nxt][0] = *(const uint4*)(Bs + pn * 512 + swB);
                    Bb[nxt][1] = *(const uint4*)(Bs + (4 + pn) * 512 + swB);
                }
                // A uint4: {a0, a2, a1, a3}; B uint4: {b0_j0, b1_j0, b0_j1, b1_j1}
#pragma unroll
                for (int i = 0; i < 4; i++) {
                    mma_f16(acc[i][0], Ab[cur][i].x, Ab[cur][i].z, Ab[cur][i].y, Ab[cur][i].w,
                            Bb[cur][0].x, Bb[cur][0].y);
                    mma_f16(acc[i][1], Ab[cur][i].x, Ab[cur][i].z, Ab[cur][i].y, Ab[cur][i].w,
                            Bb[cur][0].z, Bb[cur][0].w);
                    mma_f16(acc[i][2], Ab[cur][i].x, Ab[cur][i].z, Ab[cur][i].y, Ab[cur][i].w,
                            Bb[cur][1].x, Bb[cur][1].y);
                    mma_f16(acc[i][3], Ab[cur][i].x, Ab[cur][i].z, Ab[cur][i].y, Ab[cur][i].w,
                            Bb[cur][1].z, Bb[cur][1].w);
                }
            }
        }

        // ---- epilogue: tanh(h + b0) * W1, reduce over this 128-col group ----
        float fa[4][2];
#pragma unroll
        for (int i = 0; i < 4; i++) { fa[i][0] = 0.0f; fa[i][1] = 0.0f; }
#pragma unroll
        for (int i = 0; i < 4; i++)
#pragma unroll
            for (int f = 0; f < 4; f++) {
                const int bb = f >> 1, jj = f & 1;
#pragma unroll
                for (int c = 0; c < 4; c++) {
                    const int colg = ng * 128 + warpN * 32 + bb * 16 + jj * 8 + tig * 2 + (c & 1);
                    const float h = tanh_fast(acc[i][f][c] + s_b0[colg]);
                    fa[i][c >> 1] = fmaf(h, s_w1[colg], fa[i][c >> 1]);
                }
            }
#pragma unroll
        for (int i = 0; i < 4; i++)
#pragma unroll
            for (int hh = 0; hh < 2; hh++) {
                fa[i][hh] += __shfl_xor_sync(0xffffffffu, fa[i][hh], 1);
                fa[i][hh] += __shfl_xor_sync(0xffffffffu, fa[i][hh], 2);
            }
        if (tig == 0) {
#pragma unroll
            for (int i = 0; i < 4; i++)
#pragma unroll
                for (int hh = 0; hh < 2; hh++) {
                    const int m = warpM * 64 + i * 16 + hh * 8 + g;
                    atomicAdd(&s_F[m], fa[i][hh]);
                }
        }
    }

    __syncthreads();   // all groups' s_F contributions done
    if (tid < TILE_M) {
        if (row0 + tid < cnt) out[s_idx[tid]] = s_F[tid] + b1s;
    }
}

// ---------------- launch ----------------
extern "C" void kernel_launch(void* const* d_in, const int* in_sizes, int n_in,
                              void* d_out, int out_size) {
    const float* q  = (const float*)d_in[0];
    const int*   Z  = (const int*)d_in[1];
    const float* W0 = (const float*)d_in[2];
    const float* b0 = (const float*)d_in[3];
    const float* W1 = (const float*)d_in[4];
    const float* b1 = (const float*)d_in[5];
    float* out = (float*)d_out;
    int n = in_sizes[1];

    k_init_transpose<<<512, 256>>>(W0);
    k_scatter<<<(n + 255) / 256, 256>>>(Z, n);

    cudaFuncSetAttribute(k_gemm, cudaFuncAttributeMaxDynamicSharedMemorySize, SMEM_BYTES);
    k_gemm<<<MAX_TILES, BLOCK, SMEM_BYTES>>>(q, b0, W1, b1, out);
}

// round 13
// speedup vs baseline: 3.1867x; 1.0543x over previous
#include <cuda_runtime.h>
#include <cuda_fp16.h>
#include <cstdint>

// ---------------- problem constants ----------------
#define N_ATOMS_MAX 131072
#define DQ      256
#define H1      512
#define NTYPE   4
#define TILE_M  128
#define MAX_TILES (N_ATOMS_MAX / TILE_M + NTYPE)  // 1028
#define BLOCK   256

// ---------------- smem layout (byte offsets) ----------------
// A: [blk16 0..7][grp 0..15][lane 0..31] x 16 B   (fragment-order, lane^(grp&7) swizzle)
// B: none — B fragments are loaded LDG->register from L2-resident g_W0H
#define B_OFF_F    0                    // s_F[128] floats
#define B_OFF_IDX  512                  // s_idx[128] ints
#define B_OFF_B0   1024                 // s_b0[512] floats
#define B_OFF_W1   3072                 // s_w1[512] floats
#define B_OFF_A    5120                 // 64 KB
#define SMEM_BYTES (B_OFF_A + 65536)    // 70656 B -> 2 CTAs / SM

// ---------------- device scratch ----------------
__device__ __half g_W0H[NTYPE * H1 * DQ];      // W0^T fp16, (chunk,group)-sliced fragment order
__device__ int    g_idx[NTYPE * N_ATOMS_MAX];  // per-type regions
__device__ int    g_cnt[NTYPE];

// ---------------- helpers ----------------
static __device__ __forceinline__ float tanh_fast(float x) {
    float y;
    asm("tanh.approx.f32 %0, %1;" : "=f"(y) : "f"(x));
    return y;
}
static __device__ __forceinline__ uint32_t pack_h2(float lo, float hi) {
    uint32_t r;
    asm("cvt.rn.f16x2.f32 %0, %1, %2;" : "=r"(r) : "f"(hi), "f"(lo));
    return r;
}
static __device__ __forceinline__ void mma_f16(float* c, uint32_t a0, uint32_t a1,
                                               uint32_t a2, uint32_t a3,
                                               uint32_t b0, uint32_t b1) {
    asm volatile(
        "mma.sync.aligned.m16n8k16.row.col.f32.f16.f16.f32 "
        "{%0,%1,%2,%3}, {%4,%5,%6,%7}, {%8,%9}, {%0,%1,%2,%3};"
        : "+f"(c[0]), "+f"(c[1]), "+f"(c[2]), "+f"(c[3])
        : "r"(a0), "r"(a1), "r"(a2), "r"(a3), "r"(b0), "r"(b1));
}

// ---------------- prep 1: init counters + W0 transpose into sliced fragment-order ----
// grid 512 x 256 thr. Blocks map (kx 0..7, jy 0..15, t 0..3).
__global__ void k_init_transpose(const float* __restrict__ W0) {
    if (blockIdx.x == 0 && threadIdx.x < NTYPE) g_cnt[threadIdx.x] = 0;
    __shared__ float tile[32][33];
    const int bid = blockIdx.x;
    const int kx = bid & 7, jy = (bid >> 3) & 15, t = bid >> 7;
    const int k0 = kx * 32, j0 = jy * 32;
    const int x = threadIdx.x & 31, y0 = threadIdx.x >> 5;   // 32 x 8
#pragma unroll
    for (int dy = 0; dy < 32; dy += 8) {
        int k = k0 + y0 + dy, j = j0 + x;
        tile[y0 + dy][x] = W0[((size_t)t * DQ + k) * H1 + j];
    }
    __syncthreads();
#pragma unroll
    for (int dy = 0; dy < 32; dy += 8) {
        const int j = j0 + y0 + dy;      // H1 index (n)
        const int k = k0 + x;            // DQ index
        const int ng   = j >> 7;         // 128-col n-group
        const int blkn = (j >> 4) & 7;   // 16-col block within group
        const int gn   = blkn >> 1;      // warpN group that reads this block
        const int bb   = blkn & 1;
        const int rb   = j & 15;
        const int jj = rb >> 3, g = rb & 7;
        const int kc = k >> 6;           // 64-k chunk
        const int p  = (k >> 4) & 3;     // k16 step within chunk
        const int ki = k & 15;
        const int tg = (ki >> 1) & 3;
        const int posq = ((ki >> 3) << 1) | (ki & 1);
        const int lane = g * 4 + tg;     // no swizzle: read by LDG, not LDS
        const int ci = ng * 4 + kc;
        // (ci, gn) slice of 2048 halfs (4 KB) contiguous; lane-major 16 B fragments
        const int halfIdx = (((((ci * 4 + gn) * 2 + bb) * 4 + p) * 32 + lane) << 3) + jj * 4 + posq;
        g_W0H[(size_t)t * (H1 * DQ) + halfIdx] = __float2half_rn(tile[x][y0 + dy]);
    }
}

// ---------------- prep 2: scatter with block-aggregated atomics ----------------
__global__ void k_scatter(const int* __restrict__ Z, int n) {
    __shared__ int wcnt[8][NTYPE];
    __shared__ int wbase[8][NTYPE];
    __shared__ int blkbase[NTYPE];
    const int i = blockIdx.x * blockDim.x + threadIdx.x;
    const int lane = threadIdx.x & 31, w = threadIdx.x >> 5;
    int z = -1, rank = 0;
    if (i < n) {
        z = Z[i];
#pragma unroll
        for (int t = 0; t < NTYPE; t++) {
            unsigned m = __ballot_sync(0xffffffffu, z == t);
            if (lane == 0) wcnt[w][t] = __popc(m);
            if (z == t) rank = __popc(m & ((1u << lane) - 1u));
        }
    } else if (lane == 0) {
#pragma unroll
        for (int t = 0; t < NTYPE; t++) wcnt[w][t] = 0;
    }
    __syncthreads();
    if (threadIdx.x < NTYPE) {
        const int t = threadIdx.x;
        int s = 0;
#pragma unroll
        for (int w2 = 0; w2 < 8; w2++) { wbase[w2][t] = s; s += wcnt[w2][t]; }
        blkbase[t] = atomicAdd(&g_cnt[t], s);
    }
    __syncthreads();
    if (z >= 0) g_idx[z * N_ATOMS_MAX + blkbase[z] + wbase[w][z] + rank] = i;
}

// ---------------- main fused GEMM + tanh + dot kernel ----------------
__global__ void __launch_bounds__(BLOCK, 2)
k_gemm(const float* __restrict__ q, const float* __restrict__ b0,
       const float* __restrict__ W1, const float* __restrict__ b1v,
       float* __restrict__ out) {
    extern __shared__ char smem[];
    const int tid = threadIdx.x;
    const int wid = tid >> 5, lane = tid & 31;
    const int g = lane >> 2, tig = lane & 3;
    const int warpM = wid & 1, warpN = wid >> 1;   // 2M x 4N; warp tile 64 rows x 32 cols
    // ---- tile table from g_cnt ----
    const int c0 = g_cnt[0], c1 = g_cnt[1], c2 = g_cnt[2], c3 = g_cnt[3];
    const int n0 = (c0 + TILE_M - 1) >> 7;
    const int n1 = (c1 + TILE_M - 1) >> 7;
    const int n2 = (c2 + TILE_M - 1) >> 7;
    const int bid = blockIdx.x;
    int t, lt, cnt;
    if (bid < n0)                { t = 0; lt = bid;                cnt = c0; }
    else if (bid < n0 + n1)      { t = 1; lt = bid - n0;           cnt = c1; }
    else if (bid < n0 + n1 + n2) { t = 2; lt = bid - n0 - n1;      cnt = c2; }
    else { t = 3; lt = bid - n0 - n1 - n2; cnt = c3;
           if (lt >= (c3 + TILE_M - 1) >> 7) return; }
    const int row0 = lt * TILE_M;

    float*  s_F   = (float*)(smem + B_OFF_F);
    int*    s_idx = (int*)(smem + B_OFF_IDX);
    float*  s_b0  = (float*)(smem + B_OFF_B0);
    float*  s_w1  = (float*)(smem + B_OFF_W1);
    char*   s_A   = smem + B_OFF_A;

    const __half* w0h = g_W0H + (size_t)t * (H1 * DQ);

    if (tid < TILE_M) {
        int r = row0 + tid;
        s_idx[tid] = g_idx[t * N_ATOMS_MAX + (r < cnt ? r : row0)];
        s_F[tid] = 0.0f;
    }
#pragma unroll
    for (int o = 0; o < 2; o++) {
        const int c = o * BLOCK + tid;
        s_b0[c] = b0[t * H1 + c];
        s_w1[c] = W1[t * H1 + c];
    }
    __syncthreads();   // s_idx visible

    // A gather: 128 rows x 16 k16-groups = 2048 tasks (8/thread)
#pragma unroll
    for (int o = 0; o < 8; o++) {
        const int lin = o * BLOCK + tid;
        const int grp = lin & 15, row = lin >> 4;
        const float* src = q + (size_t)s_idx[row] * DQ + grp * 16;
        float v[16];
#pragma unroll
        for (int s = 0; s < 4; s++) {
            const float4 f4 = *(const float4*)(src + s * 4);
            v[s * 4 + 0] = f4.x; v[s * 4 + 1] = f4.y;
            v[s * 4 + 2] = f4.z; v[s * 4 + 3] = f4.w;
        }
        const int blk = row >> 4, half = (row >> 3) & 1, gg = row & 7;
        char* dbase = s_A + ((blk * 16 + grp) << 9) + half * 8;
        const int sw = grp & 7;
#pragma unroll
        for (int tt = 0; tt < 4; tt++) {
            uint2 pr;
            pr.x = pack_h2(v[tt * 2],     v[tt * 2 + 1]);
            pr.y = pack_h2(v[tt * 2 + 8], v[tt * 2 + 9]);
            *(uint2*)(dbase + (((gg * 4 + tt) ^ sw) << 4)) = pr;
        }
    }
    __syncthreads();   // A tile visible to all warps; mainloop is barrier-free

    const float b1s = b1v[0];
    const char* As_base = s_A + warpM * 64 * 512;          // + (kc*4 + i*16 + p)*512 + swA
    const char* Bg_lane = (const char*)w0h + warpN * 4096 + lane * 16;  // + ng*65536 + kc*16384 + p*512 (+2048 for bb=1)

#pragma unroll 1
    for (int ng = 0; ng < 4; ng++) {            // 128-col n-groups
        float acc[4][4][4];                     // [i: 16-row blk][f = bb*2+jj][c]
#pragma unroll
        for (int i = 0; i < 4; i++)
#pragma unroll
            for (int f = 0; f < 4; f++)
#pragma unroll
                for (int c = 0; c < 4; c++) acc[i][f][c] = 0.0f;

        const char* Bg = Bg_lane + ng * 65536;

        // 16 flattened (kc, p) steps; A from smem, B LDG->regs; double-buffered
        uint4 Ab[2][4], Bb[2][2];
        {
            const int swA = lane << 4;          // step 0: kc=0, p=0 -> swizzle term 0
#pragma unroll
            for (int i = 0; i < 4; i++)
                Ab[0][i] = *(const uint4*)(As_base + (i * 16) * 512 + swA);
            Bb[0][0] = *(const uint4*)(Bg);
            Bb[0][1] = *(const uint4*)(Bg + 2048);
        }
#pragma unroll
        for (int s = 0; s < 16; s++) {
            const int cur = s & 1, nxt = cur ^ 1;
            if (s < 15) {
                const int sn = s + 1, kcn = sn >> 2, pn = sn & 3;
                const int swA = (lane ^ (((kcn & 1) << 2) | pn)) << 4;
                const char* Asn = As_base + (kcn * 4) * 512;
#pragma unroll
                for (int i = 0; i < 4; i++)
                    Ab[nxt][i] = *(const uint4*)(Asn + (i * 16 + pn) * 512 + swA);
                const char* Bn = Bg + kcn * 16384 + pn * 512;
                Bb[nxt][0] = *(const uint4*)(Bn);
                Bb[nxt][1] = *(const uint4*)(Bn + 2048);
            }
            // A uint4: {a0, a2, a1, a3}; B uint4: {b0_j0, b1_j0, b0_j1, b1_j1}
#pragma unroll
            for (int i = 0; i < 4; i++) {
                mma_f16(acc[i][0], Ab[cur][i].x, Ab[cur][i].z, Ab[cur][i].y, Ab[cur][i].w,
                        Bb[cur][0].x, Bb[cur][0].y);
                mma_f16(acc[i][1], Ab[cur][i].x, Ab[cur][i].z, Ab[cur][i].y, Ab[cur][i].w,
                        Bb[cur][0].z, Bb[cur][0].w);
                mma_f16(acc[i][2], Ab[cur][i].x, Ab[cur][i].z, Ab[cur][i].y, Ab[cur][i].w,
                        Bb[cur][1].x, Bb[cur][1].y);
                mma_f16(acc[i][3], Ab[cur][i].x, Ab[cur][i].z, Ab[cur][i].y, Ab[cur][i].w,
                        Bb[cur][1].z, Bb[cur][1].w);
            }
        }

        // ---- epilogue: tanh(h + b0) * W1, reduce over this 128-col group ----
        float fa[4][2];
#pragma unroll
        for (int i = 0; i < 4; i++) { fa[i][0] = 0.0f; fa[i][1] = 0.0f; }
#pragma unroll
        for (int i = 0; i < 4; i++)
#pragma unroll
            for (int f = 0; f < 4; f++) {
                const int bb = f >> 1, jj = f & 1;
#pragma unroll
                for (int c = 0; c < 4; c++) {
                    const int colg = ng * 128 + warpN * 32 + bb * 16 + jj * 8 + tig * 2 + (c & 1);
                    const float h = tanh_fast(acc[i][f][c] + s_b0[colg]);
                    fa[i][c >> 1] = fmaf(h, s_w1[colg], fa[i][c >> 1]);
                }
            }
#pragma unroll
        for (int i = 0; i < 4; i++)
#pragma unroll
            for (int hh = 0; hh < 2; hh++) {
                fa[i][hh] += __shfl_xor_sync(0xffffffffu, fa[i][hh], 1);
                fa[i][hh] += __shfl_xor_sync(0xffffffffu, fa[i][hh], 2);
            }
        if (tig == 0) {
#pragma unroll
            for (int i = 0; i < 4; i++)
#pragma unroll
                for (int hh = 0; hh < 2; hh++) {
                    const int m = warpM * 64 + i * 16 + hh * 8 + g;
                    atomicAdd(&s_F[m], fa[i][hh]);
                }
        }
    }

    __syncthreads();   // all warps' s_F contributions done
    if (tid < TILE_M) {
        if (row0 + tid < cnt) out[s_idx[tid]] = s_F[tid] + b1s;
    }
}

// ---------------- launch ----------------
extern "C" void kernel_launch(void* const* d_in, const int* in_sizes, int n_in,
                              void* d_out, int out_size) {
    const float* q  = (const float*)d_in[0];
    const int*   Z  = (const int*)d_in[1];
    const float* W0 = (const float*)d_in[2];
    const float* b0 = (const float*)d_in[3];
    const float* W1 = (const float*)d_in[4];
    const float* b1 = (const float*)d_in[5];
    float* out = (float*)d_out;
    int n = in_sizes[1];

    k_init_transpose<<<512, 256>>>(W0);
    k_scatter<<<(n + 255) / 256, 256>>>(Z, n);

    cudaFuncSetAttribute(k_gemm, cudaFuncAttributeMaxDynamicSharedMemorySize, SMEM_BYTES);
    k_gemm<<<MAX_TILES, BLOCK, SMEM_BYTES>>>(q, b0, W1, b1, out);
}